// round 3
// baseline (speedup 1.0000x reference)
#include <cuda_runtime.h>
#include <cuda_bf16.h>
#include <cstdint>

// Problem constants: T=4, B=64, C=512, N=196, H=8, D=64
#define EPS_ 1e-5f

static const size_t SPK_SZ  = 3ULL * 4 * 64 * 512 * 196;   // q/k/v spikes u8
static const size_t S2_SZ   = 4ULL * 64 * 512 * 196;       // attn_lif spikes u8
static const size_t BITS_SZ = 3ULL * 4 * 64 * 8 * 196;     // packed u64 (d-bits)
static const size_t BR_BITS = 4ULL * 64 * 8 * 196;         // 401408 per branch
static const size_t O_ELEMS = 4ULL * 64 * 512 * 196;       // 25,690,112

__device__ __align__(16) unsigned char      g_spk[SPK_SZ];
__device__ __align__(16) unsigned char      g_s2[S2_SZ];
__device__ __align__(16) unsigned long long g_bits[BITS_SZ];
__device__ __align__(16) float              g_wT[4ULL * 512 * 512];
__device__ float g_inv[2048];
__device__ float g_shift[2048];

// ---------------------------------------------------------------------------
// BN prep: inv = gamma*rsqrt(var+eps); shift = beta - mean*inv
// ---------------------------------------------------------------------------
__global__ void prep_bn(const float* __restrict__ gamma, const float* __restrict__ beta,
                        const float* __restrict__ mean,  const float* __restrict__ var) {
    int i = blockIdx.x * 256 + threadIdx.x;
    if (i < 2048) {
        float inv = gamma[i] * rsqrtf(var[i] + EPS_);
        g_inv[i]   = inv;
        g_shift[i] = beta[i] - mean[i] * inv;
    }
}

// ---------------------------------------------------------------------------
// Transpose w[4][o][c] -> g_wT[4][c][o] (coalesced GEMM loads)
// ---------------------------------------------------------------------------
__global__ void transpose_w(const float* __restrict__ w) {
    __shared__ float tile[32][33];
    int z  = blockIdx.z;
    int c0 = blockIdx.x * 32, o0 = blockIdx.y * 32;
    int tx = threadIdx.x, ty = threadIdx.y;
    tile[ty][tx] = w[((size_t)z * 512 + (o0 + ty)) * 512 + (c0 + tx)];
    __syncthreads();
    g_wT[((size_t)z * 512 + (c0 + ty)) * 512 + (o0 + tx)] = tile[tx][ty];
}

// ---------------------------------------------------------------------------
// Fused GEMM + BN + LIF.
//   IS_PROJ=0: Y[t,o,n] = sum_c w[br][o][c] * x[t,b,c,n]; spikes(u8) -> g_spk
//   IS_PROJ=1: input = g_s2 (u8 spikes), br=3; final spikes(f32) -> o_out
// Block: 256 thr, tile 64o x 64n, all 4 t. Thread: 4o x 4n x 4t = 64 acc.
// ---------------------------------------------------------------------------
template<int IS_PROJ>
__global__ __launch_bounds__(256) void gemm_lif(const float* __restrict__ x,
                                                float* __restrict__ o_out) {
    const int ntile = blockIdx.x;          // 0..3 (n base = ntile*64, valid < 196)
    const int otile = blockIdx.y;          // 0..7
    int br, b;
    if (IS_PROJ) { br = 3; b = blockIdx.z; }
    else         { br = blockIdx.z >> 6; b = blockIdx.z & 63; }

    __shared__ float ws[8][64];
    __shared__ float xs[4][8][64];

    const int tid  = threadIdx.x;
    const int otid = tid >> 4;             // 0..15
    const int ntid = tid & 15;             // 0..15

    float acc[4][4][4];
#pragma unroll
    for (int t = 0; t < 4; t++)
#pragma unroll
        for (int i = 0; i < 4; i++)
#pragma unroll
            for (int j = 0; j < 4; j++) acc[t][i][j] = 0.f;

    for (int kc = 0; kc < 512; kc += 8) {
        __syncthreads();
        // W tile: 8c x 64o
        if (tid < 128) {
            int f = tid * 4; int kk = f >> 6; int o = f & 63;
            float4 wv = *(const float4*)(g_wT + ((size_t)br * 512 + kc + kk) * 512
                                              + (size_t)otile * 64 + o);
            *(float4*)&ws[kk][o] = wv;
        }
        // X tile: 4t x 8c x 64n
#pragma unroll
        for (int r = 0; r < 2; r++) {
            int e  = (tid + r * 256) * 4;
            int t  = e >> 9;
            int kk = (e >> 6) & 7;
            int n  = e & 63;
            int gn = ntile * 64 + n;
            float4 v = make_float4(0.f, 0.f, 0.f, 0.f);
            if (gn + 3 < 196) {           // 196 % 4 == 0 -> full-or-nothing
                if (IS_PROJ) {
                    unsigned int u = *(const unsigned int*)(g_s2 +
                        (((size_t)t * 64 + b) * 512 + kc + kk) * 196 + gn);
                    v = make_float4((float)(u & 255), (float)((u >> 8) & 255),
                                    (float)((u >> 16) & 255), (float)(u >> 24));
                } else {
                    v = *(const float4*)(x + (((size_t)t * 64 + b) * 512 + kc + kk) * 196 + gn);
                }
            }
            *(float4*)&xs[t][kk][n] = v;
        }
        __syncthreads();
#pragma unroll
        for (int kk = 0; kk < 8; kk++) {
            float4 wv = *(const float4*)&ws[kk][otid * 4];
            float wa[4] = {wv.x, wv.y, wv.z, wv.w};
#pragma unroll
            for (int t = 0; t < 4; t++) {
                float4 xv = *(const float4*)&xs[t][kk][ntid * 4];
                float xa[4] = {xv.x, xv.y, xv.z, xv.w};
#pragma unroll
                for (int i = 0; i < 4; i++)
#pragma unroll
                    for (int j = 0; j < 4; j++)
                        acc[t][i][j] += wa[i] * xa[j];
            }
        }
    }

    // Epilogue: BN + LIF over t (sequential), write spikes
    const int nb = ntile * 64 + ntid * 4;
    const int ob = otile * 64 + otid * 4;
    if (nb > 192) return;                  // n 196..252 fully out of range

    if (!IS_PROJ) {
#pragma unroll
        for (int i = 0; i < 4; i++) {
            int o = ob + i;
            float inv = g_inv[br * 512 + o], shf = g_shift[br * 512 + o];
            unsigned int res[4] = {0u, 0u, 0u, 0u};
#pragma unroll
            for (int j = 0; j < 4; j++) {
                float v = 0.f;
#pragma unroll
                for (int t = 0; t < 4; t++) {
                    float y = acc[t][i][j] * inv + shf;
                    v += (y - v) * 0.5f;               // v + (x - v)/TAU
                    if (v >= 1.0f) { res[t] |= 1u << (8 * j); v = 0.f; }
                }
            }
#pragma unroll
            for (int t = 0; t < 4; t++)
                *(unsigned int*)(g_spk +
                    ((((size_t)br * 4 + t) * 64 + b) * 512 + o) * 196 + nb) = res[t];
        }
    } else {
#pragma unroll
        for (int i = 0; i < 4; i++) {
            int o = ob + i;
            float inv = g_inv[1536 + o], shf = g_shift[1536 + o];
            float outv[4][4];
#pragma unroll
            for (int j = 0; j < 4; j++) {
                float v = 0.f;
#pragma unroll
                for (int t = 0; t < 4; t++) {
                    float y = acc[t][i][j] * inv + shf;
                    v += (y - v) * 0.5f;
                    bool s = (v >= 1.0f);
                    outv[t][j] = s ? 1.f : 0.f;
                    if (s) v = 0.f;
                }
            }
#pragma unroll
            for (int t = 0; t < 4; t++) {
                float4 vv = make_float4(outv[t][0], outv[t][1], outv[t][2], outv[t][3]);
                *(float4*)(o_out + (((size_t)t * 64 + b) * 512 + o) * 196 + nb) = vv;
            }
        }
    }
}

// ---------------------------------------------------------------------------
// Pack spikes over d (channel within head) into u64: g_bits[br,t,b,h,n]
// ---------------------------------------------------------------------------
__global__ void pack_bits() {
    int idx = blockIdx.x * 256 + threadIdx.x;
    if (idx >= (int)BITS_SZ) return;
    int n = idx % 196; int r = idx / 196;
    int h = r & 7;  r >>= 3;
    int b = r & 63; r >>= 6;
    int t = r & 3;  int br = r >> 2;
    const unsigned char* base = g_spk +
        ((((size_t)br * 4 + t) * 64 + b) * 512 + h * 64) * 196 + n;
    unsigned long long w = 0ull;
#pragma unroll
    for (int d = 0; d < 64; d++)
        w |= (unsigned long long)(base[(size_t)d * 196] & 1) << d;
    g_bits[idx] = w;
}

// ---------------------------------------------------------------------------
// Attention per (b,h): all 4 t in-block (LIF state in regs).
//   attn[n,m] = popc(q_n & k_m)*0.125  (written to d_out)
//   o1[n,d]   = 0.125 * sum_{e set in q_n} cnt[e][d],
//   cnt[e][d] = popc over m of (k[:,e] & v[:,d])   -- exact integers
//   then attn_lif (th=0.5) -> g_s2 spikes (staged via shared to coalesce)
// ---------------------------------------------------------------------------
__global__ __launch_bounds__(512) void attn_kernel(float* __restrict__ attn_out) {
    const int bh = blockIdx.x;
    const int b = bh >> 3, h = bh & 7;

    __shared__ unsigned long long sq[200], sk[200], sv[200];
    __shared__ unsigned long long kcol[64][4], vcol[64][4];
    __shared__ unsigned short s_cnt[4096];
    __shared__ unsigned char  s_spk[64 * 212];   // pitch 212 (53 words, odd) no conflicts

    const int tid = threadIdx.x;
    const int d = tid & 63, g = tid >> 6;        // d-lane, n-group

    float vst[25];
#pragma unroll
    for (int j = 0; j < 25; j++) vst[j] = 0.f;

    for (int t = 0; t < 4; t++) {
        size_t qidx = ((size_t)(t * 64 + b) * 8 + h) * 196;
        // stage q/k/v bit rows (+zero pad)
        for (int i = tid; i < 600; i += 512) {
            if (i < 196)      sq[i]       = g_bits[qidx + i];
            else if (i < 392) sk[i - 196] = g_bits[BR_BITS + qidx + (i - 196)];
            else if (i < 588) sv[i - 392] = g_bits[2 * BR_BITS + qidx + (i - 392)];
            else {
                int j = i - 588;
                if (j < 4)      sq[196 + j] = 0ull;
                else if (j < 8) sk[192 + j] = 0ull;
                else            sv[188 + j] = 0ull;
            }
        }
        __syncthreads();
        // column-packed k,v (bit over m)
        {
            int e = tid & 63, wd = (tid >> 6) & 3, sel = tid >> 8;
            const unsigned long long* src = sel ? sv : sk;
            int m0 = wd * 64;
            int m1 = m0 + 64 < 196 ? m0 + 64 : 196;
            unsigned long long a = 0ull;
            for (int m = m0; m < m1; m++)
                a |= ((src[m] >> e) & 1ull) << (m - m0);
            if (sel) vcol[e][wd] = a; else kcol[e][wd] = a;
        }
        __syncthreads();
        // attn output (coalesced over m)
        size_t abase = ((size_t)(t * 64 + b) * 8 + h) * 38416;
        for (int i = tid; i < 38416; i += 512) {
            int n = i / 196; int m = i - n * 196;
            int a = __popcll(sq[n] & sk[m]);
            attn_out[abase + i] = (float)a * 0.125f;
        }
        // cnt[e][d]
        for (int i = tid; i < 4096; i += 512) {
            int e = i >> 6, dd = i & 63;
            int s = __popcll(kcol[e][0] & vcol[dd][0]) + __popcll(kcol[e][1] & vcol[dd][1])
                  + __popcll(kcol[e][2] & vcol[dd][2]) + __popcll(kcol[e][3] & vcol[dd][3]);
            s_cnt[i] = (unsigned short)s;
        }
        __syncthreads();
        // o1 + attn_lif (th=0.5); warp-uniform q walk (same n across warp)
#pragma unroll 1
        for (int j = 0; j < 25; j++) {
            int n = g + 8 * j;
            if (n < 196) {
                unsigned long long q = sq[n];
                int sum = 0;
                while (q) {
                    int e = __ffsll((long long)q) - 1;
                    q &= q - 1;
                    sum += s_cnt[(e << 6) + d];
                }
                float o1 = (float)sum * 0.125f;
                float vv = vst[j];
                vv += (o1 - vv) * 0.5f;
                bool s = (vv >= 0.5f);
                vst[j] = s ? 0.f : vv;
                s_spk[d * 212 + n] = s ? 1 : 0;
            }
        }
        __syncthreads();
        // flush staged spikes to g_s2 (coalesced rows)
        for (int i = tid; i < 64 * 196; i += 512) {
            int dd = i / 196, n = i - dd * 196;
            g_s2[(((size_t)(t * 64 + b)) * 512 + h * 64 + dd) * 196 + n] = s_spk[dd * 212 + n];
        }
        __syncthreads();
    }
}

// ---------------------------------------------------------------------------
extern "C" void kernel_launch(void* const* d_in, const int* in_sizes, int n_in,
                              void* d_out, int out_size) {
    const float* x     = (const float*)d_in[0];
    // d_in[1] = res_attn (zeros, unused by reference math)
    const float* w     = (const float*)d_in[2];
    const float* gamma = (const float*)d_in[3];
    const float* beta  = (const float*)d_in[4];
    const float* mean  = (const float*)d_in[5];
    const float* var   = (const float*)d_in[6];

    float* o_out    = (float*)d_out;
    float* attn_out = o_out + O_ELEMS;   // tuple (o, attn) flattened in order

    prep_bn<<<8, 256>>>(gamma, beta, mean, var);
    transpose_w<<<dim3(16, 16, 4), dim3(32, 32)>>>(w);
    gemm_lif<0><<<dim3(4, 8, 192), 256>>>(x, nullptr);          // QKV + BN + LIF
    pack_bits<<<(int)((BITS_SZ + 255) / 256), 256>>>();
    attn_kernel<<<512, 512>>>(attn_out);                         // attn + AV + attn_lif
    gemm_lif<1><<<dim3(4, 8, 64), 256>>>(nullptr, o_out);        // proj + BN + LIF
}

// round 5
// speedup vs baseline: 1.6404x; 1.6404x over previous
#include <cuda_runtime.h>
#include <cuda_bf16.h>
#include <cstdint>

// T=4, B=64, C=512, N=196, H=8, D=64
#define EPS_    1e-5f
#define MARGIN_ 5e-4f

constexpr size_t SPK_SZ  = 3ULL * 4 * 64 * 512 * 196;   // q/k/v spikes u8
constexpr size_t BITS_SZ = 3ULL * 4 * 64 * 8 * 196;     // packed u64
constexpr size_t BR_BITS = 4ULL * 64 * 8 * 196;
constexpr size_t O_ELEMS = 4ULL * 64 * 512 * 196;
constexpr size_t XT_SZ   = 4ULL * 64 * 196 * 512;       // transposed [t,b,n,c]
constexpr int CAP0 = 1 << 20;
constexpr int CAP1 = 1 << 18;

__device__ __align__(16) unsigned char      g_spk[SPK_SZ];
__device__ __align__(16) unsigned long long g_bits[BITS_SZ];
__device__ __align__(16) float              g_xT[XT_SZ];    // x transposed fp32
__device__ __align__(16) float              g_s2t[XT_SZ];   // attn_lif spikes f32 transposed
__device__ __align__(16) __nv_bfloat16      g_wh[2048 * 512];
__device__ __align__(16) __nv_bfloat16      g_wl[2048 * 512];
__device__ float    g_inv[2048];
__device__ float    g_shift[2048];
__device__ unsigned g_fix0[CAP0];
__device__ unsigned g_fix1[CAP1];
__device__ int      g_cnt[2];

// ---------------------------------------------------------------------------
__global__ void zero_cnt() { if (threadIdx.x < 2) g_cnt[threadIdx.x] = 0; }

__global__ void prep_bn(const float* __restrict__ gamma, const float* __restrict__ beta,
                        const float* __restrict__ mean,  const float* __restrict__ var) {
    int i = blockIdx.x * 256 + threadIdx.x;
    if (i < 2048) {
        float inv = gamma[i] * rsqrtf(var[i] + EPS_);
        g_inv[i]   = inv;
        g_shift[i] = beta[i] - mean[i] * inv;
    }
}

// w[4][o][c] -> hi/lo bf16 split
__global__ void w_split(const float* __restrict__ w) {
    int i = blockIdx.x * 256 + threadIdx.x;
    float f = w[i];
    __nv_bfloat16 h = __float2bfloat16(f);
    g_wh[i] = h;
    g_wl[i] = __float2bfloat16(f - __bfloat162float(h));
}

// x [t,b,c,n] -> g_xT [t,b,n,c] fp32
__global__ void x_transpose(const float* __restrict__ x) {
    __shared__ float tile[32][33];
    int tb = blockIdx.z;
    int c0 = blockIdx.x * 32, n0 = blockIdx.y * 32;
#pragma unroll
    for (int i = 0; i < 4; i++) {
        int c = threadIdx.y + i * 8, n = threadIdx.x;
        float v = (n0 + n < 196) ? x[((size_t)tb * 512 + c0 + c) * 196 + n0 + n] : 0.f;
        tile[c][n] = v;
    }
    __syncthreads();
#pragma unroll
    for (int i = 0; i < 4; i++) {
        int n = threadIdx.y + i * 8, c = threadIdx.x;
        if (n0 + n < 196)
            g_xT[((size_t)tb * 196 + n0 + n) * 512 + c0 + c] = tile[c][n];
    }
}

// ---------------------------------------------------------------------------
__device__ __forceinline__ void ldsm4(uint32_t addr, uint32_t* d) {
    asm volatile("ldmatrix.sync.aligned.m8n8.x4.shared.b16 {%0,%1,%2,%3}, [%4];"
        : "=r"(d[0]), "=r"(d[1]), "=r"(d[2]), "=r"(d[3]) : "r"(addr));
}
__device__ __forceinline__ void mma_bf16(float* c, const uint32_t* a, const uint32_t* b) {
    asm volatile(
        "mma.sync.aligned.m16n8k16.row.col.f32.bf16.bf16.f32 "
        "{%0,%1,%2,%3}, {%4,%5,%6,%7}, {%8,%9}, {%0,%1,%2,%3};"
        : "+f"(c[0]), "+f"(c[1]), "+f"(c[2]), "+f"(c[3])
        : "r"(a[0]), "r"(a[1]), "r"(a[2]), "r"(a[3]), "r"(b[0]), "r"(b[1]));
}
__device__ __forceinline__ uint32_t pack_bf2(__nv_bfloat16 a, __nv_bfloat16 b) {
    __nv_bfloat162 t = __halves2bfloat162(a, b);
    return *(uint32_t*)&t;
}

// ---------------------------------------------------------------------------
// Tensor-core GEMM + BN + LIF (+ borderline detection). Tile 128o x 32n x 4t.
// ---------------------------------------------------------------------------
template<int IS_PROJ>
__global__ __launch_bounds__(256) void mma_gemm_lif(float* __restrict__ o_out) {
    const int ntile = blockIdx.x;
    const int o128  = blockIdx.y << 7;
    const int b     = blockIdx.z;
    const int n0    = ntile << 5;
    const int tid = threadIdx.x, lane = tid & 31, warp = tid >> 5;
    const int wt = warp & 3, oh = warp >> 2;
    const int wrow0 = IS_PROJ ? 1536 : 0;
    const float* __restrict__ xsrc = IS_PROJ ? g_s2t : g_xT;

    __shared__ __align__(16) unsigned char SM[41216];
    __nv_bfloat16* wsh = (__nv_bfloat16*)(SM);            // [128][40] pitch 80B
    __nv_bfloat16* wsl = (__nv_bfloat16*)(SM + 10240);
    __nv_bfloat16* xsh = (__nv_bfloat16*)(SM + 20480);    // [4][32][40]
    __nv_bfloat16* xsl = (__nv_bfloat16*)(SM + 30720);
    float* ys = (float*)SM;                               // epilogue [4][64][33]

    float acc[4][4][4];
#pragma unroll
    for (int a = 0; a < 4; a++)
#pragma unroll
        for (int c = 0; c < 4; c++)
#pragma unroll
            for (int d = 0; d < 4; d++) acc[a][c][d] = 0.f;

    const int aRow = lane & 15,                aK = (lane >> 4) << 3;
    const int bRow = (lane & 7) | ((lane >> 4) << 3), bK = ((lane >> 3) & 1) << 3;

    const uint32_t sb  = (uint32_t)__cvta_generic_to_shared(SM);
    const uint32_t s_wh = sb, s_wl = sb + 10240;
    const uint32_t s_xh = sb + 20480 + wt * 32 * 80;
    const uint32_t s_xl = sb + 30720 + wt * 32 * 80;

    const int xr = tid >> 3, xq = tid & 7;

    for (int kc = 0; kc < 512; kc += 32) {
        __syncthreads();
#pragma unroll
        for (int p = 0; p < 2; p++) {
            int idx = tid + (p << 8);
            int r = idx >> 2, q = idx & 3;
            size_t go = (size_t)(wrow0 + o128 + r) * 512 + kc + (q << 3);
            *(uint4*)(wsh + r * 40 + (q << 3)) = *(const uint4*)(g_wh + go);
            *(uint4*)(wsl + r * 40 + (q << 3)) = *(const uint4*)(g_wl + go);
        }
#pragma unroll
        for (int t = 0; t < 4; t++) {
            float4 v = make_float4(0.f, 0.f, 0.f, 0.f);
            if (n0 + xr < 196)
                v = *(const float4*)(xsrc + ((size_t)((t * 64 + b) * 196 + n0 + xr)) * 512
                                     + kc + (xq << 2));
            __nv_bfloat16 h0 = __float2bfloat16(v.x), h1 = __float2bfloat16(v.y);
            __nv_bfloat16 h2 = __float2bfloat16(v.z), h3 = __float2bfloat16(v.w);
            *(uint2*)(xsh + (t * 32 + xr) * 40 + (xq << 2)) =
                make_uint2(pack_bf2(h0, h1), pack_bf2(h2, h3));
            if (!IS_PROJ) {
                __nv_bfloat16 l0 = __float2bfloat16(v.x - __bfloat162float(h0));
                __nv_bfloat16 l1 = __float2bfloat16(v.y - __bfloat162float(h1));
                __nv_bfloat16 l2 = __float2bfloat16(v.z - __bfloat162float(h2));
                __nv_bfloat16 l3 = __float2bfloat16(v.w - __bfloat162float(h3));
                *(uint2*)(xsl + (t * 32 + xr) * 40 + (xq << 2)) =
                    make_uint2(pack_bf2(l0, l1), pack_bf2(l2, l3));
            }
        }
        __syncthreads();
#pragma unroll
        for (int kk = 0; kk < 32; kk += 16) {
            uint32_t Ah[4][4], Bh[4][2];
#pragma unroll
            for (int ot = 0; ot < 4; ot++)
                ldsm4(s_wh + ((oh * 64 + ot * 16 + aRow) * 40 + kk + aK) * 2, Ah[ot]);
#pragma unroll
            for (int n2 = 0; n2 < 2; n2++) {
                uint32_t d[4];
                ldsm4(s_xh + ((n2 * 16 + bRow) * 40 + kk + bK) * 2, d);
                Bh[n2 * 2][0] = d[0]; Bh[n2 * 2][1] = d[1];
                Bh[n2 * 2 + 1][0] = d[2]; Bh[n2 * 2 + 1][1] = d[3];
            }
#pragma unroll
            for (int ot = 0; ot < 4; ot++)
#pragma unroll
                for (int nt = 0; nt < 4; nt++) mma_bf16(acc[ot][nt], Ah[ot], Bh[nt]);
            if (!IS_PROJ) {
                uint32_t Bl[4][2];
#pragma unroll
                for (int n2 = 0; n2 < 2; n2++) {
                    uint32_t d[4];
                    ldsm4(s_xl + ((n2 * 16 + bRow) * 40 + kk + bK) * 2, d);
                    Bl[n2 * 2][0] = d[0]; Bl[n2 * 2][1] = d[1];
                    Bl[n2 * 2 + 1][0] = d[2]; Bl[n2 * 2 + 1][1] = d[3];
                }
#pragma unroll
                for (int ot = 0; ot < 4; ot++)
#pragma unroll
                    for (int nt = 0; nt < 4; nt++) mma_bf16(acc[ot][nt], Ah[ot], Bl[nt]);
            }
            uint32_t Al[4][4];
#pragma unroll
            for (int ot = 0; ot < 4; ot++)
                ldsm4(s_wl + ((oh * 64 + ot * 16 + aRow) * 40 + kk + aK) * 2, Al[ot]);
#pragma unroll
            for (int ot = 0; ot < 4; ot++)
#pragma unroll
                for (int nt = 0; nt < 4; nt++) mma_bf16(acc[ot][nt], Al[ot], Bh[nt]);
        }
    }

    __syncthreads();
    const int cg = lane >> 2, ctg = lane & 3;
#pragma unroll 1
    for (int pass = 0; pass < 2; pass++) {
        if (oh == pass) {
#pragma unroll
            for (int ot = 0; ot < 4; ot++)
#pragma unroll
                for (int nt = 0; nt < 4; nt++) {
                    int row = ot * 16 + cg, col = nt * 8 + ctg * 2;
                    ys[(wt * 64 + row) * 33 + col]         = acc[ot][nt][0];
                    ys[(wt * 64 + row) * 33 + col + 1]     = acc[ot][nt][1];
                    ys[(wt * 64 + row + 8) * 33 + col]     = acc[ot][nt][2];
                    ys[(wt * 64 + row + 8) * 33 + col + 1] = acc[ot][nt][3];
                }
        }
        __syncthreads();
        {
            const int o_loc = tid >> 2, nq = tid & 3;
            const int og = o128 + pass * 64 + o_loc;
            const int br = IS_PROJ ? 3 : (og >> 9);
            const int o_in = IS_PROJ ? og : (og & 511);
            const float inv = g_inv[br * 512 + o_in], shf = g_shift[br * 512 + o_in];
#pragma unroll
            for (int j = 0; j < 8; j++) {
                int nl = nq * 8 + j, gn = n0 + nl;
                if (gn < 196) {
                    float v = 0.f;
                    bool bad = false;
                    float fs[4];
#pragma unroll
                    for (int t = 0; t < 4; t++) {
                        float y = fmaf(ys[(t * 64 + o_loc) * 33 + nl], inv, shf);
                        v += (y - v) * 0.5f;
                        float d = v - 1.0f;
                        if (fabsf(d) < MARGIN_) bad = true;
                        bool s = d >= 0.f;
                        fs[t] = s ? 1.f : 0.f;
                        if (s) v = 0.f;
                    }
                    if (IS_PROJ) {
#pragma unroll
                        for (int t = 0; t < 4; t++)
                            o_out[((size_t)(t * 64 + b) * 512 + o_in) * 196 + gn] = fs[t];
                    } else {
#pragma unroll
                        for (int t = 0; t < 4; t++)
                            g_spk[((((size_t)br * 4 + t) * 64 + b) * 512 + o_in) * 196 + gn] =
                                (unsigned char)(fs[t] != 0.f);
                    }
                    if (bad) {
                        if (IS_PROJ) {
                            int s = atomicAdd(&g_cnt[1], 1);
                            if (s < CAP1)
                                g_fix1[s] = ((unsigned)b << 17) | ((unsigned)o_in << 8) | gn;
                        } else {
                            int s = atomicAdd(&g_cnt[0], 1);
                            if (s < CAP0)
                                g_fix0[s] = ((unsigned)br << 23) | ((unsigned)b << 17) |
                                            ((unsigned)o_in << 8) | gn;
                        }
                    }
                }
            }
        }
        __syncthreads();
    }
}

// ---------------------------------------------------------------------------
// Fixup: exact fp32 recompute of borderline LIF chains, STRICT SEQUENTIAL
// summation order over c=0..511 (identical to the R2 kernel that matched the
// reference bit-for-bit). One thread per entry, grid-stride.
// ---------------------------------------------------------------------------
template<int IS_PROJ>
__global__ void fixup(const float* __restrict__ w, float* __restrict__ o_out) {
    int cnt = g_cnt[IS_PROJ];
    int cap = IS_PROJ ? CAP1 : CAP0;
    if (cnt > cap) cnt = cap;
    const float* __restrict__ xs = IS_PROJ ? g_s2t : g_xT;
    for (int e = blockIdx.x * blockDim.x + threadIdx.x; e < cnt;
         e += gridDim.x * blockDim.x) {
        unsigned u = IS_PROJ ? g_fix1[e] : g_fix0[e];
        int n = u & 255, o = (u >> 8) & 511, bb = (u >> 17) & 63;
        int br = IS_PROJ ? 3 : (int)(u >> 23);
        const float* wr = w + ((size_t)br * 512 + o) * 512;
        float inv = g_inv[br * 512 + o], shf = g_shift[br * 512 + o];
        float v = 0.f;
#pragma unroll 1
        for (int t = 0; t < 4; t++) {
            const float* xr = xs + ((size_t)((t * 64 + bb) * 196 + n)) * 512;
            float s = 0.f;
#pragma unroll 4
            for (int c = 0; c < 512; c += 4) {
                float4 a  = *(const float4*)(wr + c);
                float4 xv = *(const float4*)(xr + c);
                s = fmaf(a.x, xv.x, s);
                s = fmaf(a.y, xv.y, s);
                s = fmaf(a.z, xv.z, s);
                s = fmaf(a.w, xv.w, s);
            }
            float y = fmaf(s, inv, shf);
            v += (y - v) * 0.5f;
            bool sp = (v - 1.0f) >= 0.f;
            if (IS_PROJ)
                o_out[((size_t)(t * 64 + bb) * 512 + o) * 196 + n] = sp ? 1.f : 0.f;
            else
                g_spk[((((size_t)br * 4 + t) * 64 + bb) * 512 + o) * 196 + n] = sp ? 1 : 0;
            if (sp) v = 0.f;
        }
    }
}

// ---------------------------------------------------------------------------
__global__ void pack_bits() {
    int idx = blockIdx.x * 256 + threadIdx.x;
    if (idx >= (int)BITS_SZ) return;
    int n = idx % 196; int r = idx / 196;
    int h = r & 7;  r >>= 3;
    int b = r & 63; r >>= 6;
    int t = r & 3;  int br = r >> 2;
    const unsigned char* base = g_spk +
        ((((size_t)br * 4 + t) * 64 + b) * 512 + h * 64) * 196 + n;
    unsigned long long w = 0ull;
#pragma unroll
    for (int d = 0; d < 64; d++)
        w |= (unsigned long long)(base[(size_t)d * 196] & 1) << d;
    g_bits[idx] = w;
}

// ---------------------------------------------------------------------------
// Attention per (b,h), all 4 t in-block. Exact integer popcount math.
// ---------------------------------------------------------------------------
__global__ __launch_bounds__(512) void attn_kernel(float* __restrict__ attn_out) {
    const int bh = blockIdx.x;
    const int b = bh >> 3, h = bh & 7;

    __shared__ unsigned long long sq[200], sk[200], sv[200];
    __shared__ unsigned long long kcol[64][4], vcol[64][4];
    __shared__ unsigned short s_cnt[4096];
    __shared__ unsigned char  s_spk[64 * 212];

    const int tid = threadIdx.x;
    const int d = tid & 63, g = tid >> 6;

    float vst[25];
#pragma unroll
    for (int j = 0; j < 25; j++) vst[j] = 0.f;

    for (int t = 0; t < 4; t++) {
        size_t qidx = ((size_t)(t * 64 + b) * 8 + h) * 196;
        for (int i = tid; i < 600; i += 512) {
            if (i < 196)      sq[i]       = g_bits[qidx + i];
            else if (i < 392) sk[i - 196] = g_bits[BR_BITS + qidx + (i - 196)];
            else if (i < 588) sv[i - 392] = g_bits[2 * BR_BITS + qidx + (i - 392)];
            else {
                int j = i - 588;
                if (j < 4)      sq[196 + j] = 0ull;
                else if (j < 8) sk[192 + j] = 0ull;
                else            sv[188 + j] = 0ull;
            }
        }
        __syncthreads();
        {
            int e = tid & 63, wd = (tid >> 6) & 3, sel = tid >> 8;
            const unsigned long long* src = sel ? sv : sk;
            int m0 = wd * 64;
            int m1 = m0 + 64 < 196 ? m0 + 64 : 196;
            unsigned long long a = 0ull;
            for (int m = m0; m < m1; m++)
                a |= ((src[m] >> e) & 1ull) << (m - m0);
            if (sel) vcol[e][wd] = a; else kcol[e][wd] = a;
        }
        __syncthreads();
        size_t abase = ((size_t)(t * 64 + b) * 8 + h) * 38416;
        for (int i = tid; i < 38416; i += 512) {
            int n = i / 196; int m = i - n * 196;
            attn_out[abase + i] = (float)__popcll(sq[n] & sk[m]) * 0.125f;
        }
        for (int i = tid; i < 4096; i += 512) {
            int e = i >> 6, dd = i & 63;
            int s = __popcll(kcol[e][0] & vcol[dd][0]) + __popcll(kcol[e][1] & vcol[dd][1])
                  + __popcll(kcol[e][2] & vcol[dd][2]) + __popcll(kcol[e][3] & vcol[dd][3]);
            s_cnt[i] = (unsigned short)s;
        }
        __syncthreads();
#pragma unroll 1
        for (int j = 0; j < 25; j++) {
            int n = g + 8 * j;
            if (n < 196) {
                unsigned long long q = sq[n];
                int sum = 0;
                while (q) {
                    int e = __ffsll((long long)q) - 1;
                    q &= q - 1;
                    sum += s_cnt[(e << 6) + d];
                }
                float o1 = (float)sum * 0.125f;
                float vv = vst[j];
                vv += (o1 - vv) * 0.5f;
                bool s = (vv >= 0.5f);
                vst[j] = s ? 0.f : vv;
                s_spk[d * 212 + n] = s ? 1 : 0;
            }
        }
        __syncthreads();
        for (int i = tid; i < 196 * 64; i += 512) {
            int n = i >> 6, dd = i & 63;
            g_s2t[((size_t)((t * 64 + b) * 196 + n)) * 512 + h * 64 + dd] =
                (float)s_spk[dd * 212 + n];
        }
        __syncthreads();
    }
}

// ---------------------------------------------------------------------------
extern "C" void kernel_launch(void* const* d_in, const int* in_sizes, int n_in,
                              void* d_out, int out_size) {
    const float* x     = (const float*)d_in[0];
    const float* w     = (const float*)d_in[2];
    const float* gamma = (const float*)d_in[3];
    const float* beta  = (const float*)d_in[4];
    const float* mean  = (const float*)d_in[5];
    const float* var   = (const float*)d_in[6];

    float* o_out    = (float*)d_out;
    float* attn_out = o_out + O_ELEMS;

    zero_cnt<<<1, 32>>>();                                 // 1
    zero_cnt<<<1, 32>>>();                                 // 2 (idempotent; aligns ncu -s 5)
    prep_bn<<<8, 256>>>(gamma, beta, mean, var);           // 3
    w_split<<<4096, 256>>>(w);                             // 4
    x_transpose<<<dim3(16, 7, 256), dim3(32, 8)>>>(x);     // 5
    mma_gemm_lif<0><<<dim3(7, 12, 64), 256>>>(nullptr);    // 6 <- ncu captures this
    fixup<0><<<256, 256>>>(w, nullptr);
    pack_bits<<<4704, 256>>>();
    attn_kernel<<<512, 512>>>(attn_out);
    mma_gemm_lif<1><<<dim3(7, 4, 64), 256>>>(o_out);
    fixup<1><<<64, 256>>>(w, o_out);
}

// round 6
// speedup vs baseline: 1.9239x; 1.1728x over previous
#include <cuda_runtime.h>
#include <cuda_bf16.h>
#include <cstdint>

// T=4, B=64, C=512, N=196, H=8, D=64
#define EPS_    1e-5f
#define MARGIN_ 5e-4f

constexpr size_t SPK_SZ  = 3ULL * 4 * 64 * 512 * 196;   // q/k/v spikes u8
constexpr size_t BITS_SZ = 3ULL * 4 * 64 * 8 * 196;     // packed u64
constexpr size_t BR_BITS = 4ULL * 64 * 8 * 196;
constexpr size_t O_ELEMS = 4ULL * 64 * 512 * 196;
constexpr size_t XT_SZ   = 4ULL * 64 * 196 * 512;       // [t,b,n,c]
constexpr int CAP0 = 1 << 20;
constexpr int CAP1 = 1 << 18;
constexpr int STAGE_B = 40960;                          // bytes per pipeline stage

__device__ __align__(16) unsigned char      g_spk[SPK_SZ];
__device__ __align__(16) unsigned long long g_bits[BITS_SZ];
__device__ __align__(16) float              g_xT[XT_SZ];     // fp32 (fixup only)
__device__ __align__(16) __nv_bfloat16      g_xh[XT_SZ];
__device__ __align__(16) __nv_bfloat16      g_xl[XT_SZ];
__device__ __align__(16) __nv_bfloat16      g_s2h[XT_SZ];    // attn_lif spikes bf16
__device__ __align__(16) __nv_bfloat16      g_wh[2048 * 512];
__device__ __align__(16) __nv_bfloat16      g_wl[2048 * 512];
__device__ float    g_inv[2048];
__device__ float    g_shift[2048];
__device__ unsigned g_fix0[CAP0];
__device__ unsigned g_fix1[CAP1];
__device__ int      g_cnt[2];

// ---------------------------------------------------------------------------
__global__ void prep_bn(const float* __restrict__ gamma, const float* __restrict__ beta,
                        const float* __restrict__ mean,  const float* __restrict__ var) {
    int i = blockIdx.x * 256 + threadIdx.x;
    if (blockIdx.x == 0 && threadIdx.x < 2) g_cnt[threadIdx.x] = 0;
    if (i < 2048) {
        float inv = gamma[i] * rsqrtf(var[i] + EPS_);
        g_inv[i]   = inv;
        g_shift[i] = beta[i] - mean[i] * inv;
    }
}

__global__ void w_split(const float* __restrict__ w) {
    int i = blockIdx.x * 256 + threadIdx.x;
    float f = w[i];
    __nv_bfloat16 h = __float2bfloat16(f);
    g_wh[i] = h;
    g_wl[i] = __float2bfloat16(f - __bfloat162float(h));
}

// x [t,b,c,n] -> g_xT f32 + g_xh/g_xl bf16, all [t,b,n,c]
__global__ void x_split(const float* __restrict__ x) {
    __shared__ float tile[32][33];
    int tb = blockIdx.z;
    int c0 = blockIdx.x * 32, n0 = blockIdx.y * 32;
#pragma unroll
    for (int i = 0; i < 4; i++) {
        int c = threadIdx.y + i * 8, n = threadIdx.x;
        float v = (n0 + n < 196) ? x[((size_t)tb * 512 + c0 + c) * 196 + n0 + n] : 0.f;
        tile[c][n] = v;
    }
    __syncthreads();
#pragma unroll
    for (int i = 0; i < 4; i++) {
        int n = threadIdx.y + i * 8, c = threadIdx.x;
        if (n0 + n < 196) {
            size_t idx = ((size_t)tb * 196 + n0 + n) * 512 + c0 + c;
            float v = tile[c][n];
            __nv_bfloat16 h = __float2bfloat16(v);
            g_xT[idx] = v;
            g_xh[idx] = h;
            g_xl[idx] = __float2bfloat16(v - __bfloat162float(h));
        }
    }
}

// ---------------------------------------------------------------------------
__device__ __forceinline__ void ldsm4(uint32_t addr, uint32_t* d) {
    asm volatile("ldmatrix.sync.aligned.m8n8.x4.shared.b16 {%0,%1,%2,%3}, [%4];"
        : "=r"(d[0]), "=r"(d[1]), "=r"(d[2]), "=r"(d[3]) : "r"(addr));
}
__device__ __forceinline__ void mma_bf16(float* c, const uint32_t* a, const uint32_t* b) {
    asm volatile(
        "mma.sync.aligned.m16n8k16.row.col.f32.bf16.bf16.f32 "
        "{%0,%1,%2,%3}, {%4,%5,%6,%7}, {%8,%9}, {%0,%1,%2,%3};"
        : "+f"(c[0]), "+f"(c[1]), "+f"(c[2]), "+f"(c[3])
        : "r"(a[0]), "r"(a[1]), "r"(a[2]), "r"(a[3]), "r"(b[0]), "r"(b[1]));
}
__device__ __forceinline__ void cpa16(uint32_t dst, const void* src, int sz) {
    asm volatile("cp.async.cg.shared.global [%0], [%1], 16, %2;"
                 :: "r"(dst), "l"(src), "r"(sz));
}

// ---------------------------------------------------------------------------
// Tensor-core GEMM + BN + LIF, cp.async double-buffered. Tile 128o x 32n x 4t.
// Stage layout (per stage, pitch 40 elem = 80B rows):
//   +0      Wh [128][40]      +10240  Wl [128][40]
//   +20480  Xh [4t*32n][40]   +30720  Xl (QKV only)
// ---------------------------------------------------------------------------
template<int IS_PROJ>
__global__ __launch_bounds__(256) void mma_gemm_lif(float* __restrict__ o_out) {
    extern __shared__ __align__(16) unsigned char SM[];
    const int ntile = blockIdx.x;
    const int o128  = blockIdx.y << 7;
    const int b     = blockIdx.z;
    const int n0    = ntile << 5;
    const int tid = threadIdx.x, lane = tid & 31, warp = tid >> 5;
    const int wt = warp & 3, oh = warp >> 2;
    const int wrow0 = IS_PROJ ? 1536 : 0;
    const __nv_bfloat16* __restrict__ xh = IS_PROJ ? g_s2h : g_xh;

    const uint32_t sb = (uint32_t)__cvta_generic_to_shared(SM);

    // per-thread staging coordinates (2 chunks of 16B per array)
    const int c0i = tid * 2, c1i = tid * 2 + 1;
    const int wr0 = c0i >> 2, wq0 = c0i & 3, wr1 = c1i >> 2, wq1 = c1i & 3;
    const int xt0 = wr0 >> 5, xn0 = wr0 & 31, xt1 = wr1 >> 5, xn1 = wr1 & 31;
    const int gn0 = n0 + xn0, gn1 = n0 + xn1;
    const int sz0 = gn0 < 196 ? 16 : 0, sz1 = gn1 < 196 ? 16 : 0;
    const size_t xrow0 = ((size_t)((xt0 * 64 + b) * 196 + (gn0 < 196 ? gn0 : 0))) * 512;
    const size_t xrow1 = ((size_t)((xt1 * 64 + b) * 196 + (gn1 < 196 ? gn1 : 0))) * 512;
    const size_t wrow_a = (size_t)(wrow0 + o128 + wr0) * 512;
    const size_t wrow_b = (size_t)(wrow0 + o128 + wr1) * 512;

    float acc[4][4][4];
#pragma unroll
    for (int a = 0; a < 4; a++)
#pragma unroll
        for (int c = 0; c < 4; c++)
#pragma unroll
            for (int d = 0; d < 4; d++) acc[a][c][d] = 0.f;

    const int aRow = lane & 15,                aK = (lane >> 4) << 3;
    const int bRow = (lane & 7) | ((lane >> 4) << 3), bK = ((lane >> 3) & 1) << 3;

#define STAGE_LOAD(ST, KC)                                                          \
    do {                                                                            \
        uint32_t s0 = sb + (ST) * STAGE_B;                                          \
        cpa16(s0 + wr0 * 80 + wq0 * 16, g_wh + wrow_a + (KC) + wq0 * 8, 16);        \
        cpa16(s0 + wr1 * 80 + wq1 * 16, g_wh + wrow_b + (KC) + wq1 * 8, 16);        \
        cpa16(s0 + 10240 + wr0 * 80 + wq0 * 16, g_wl + wrow_a + (KC) + wq0 * 8, 16);\
        cpa16(s0 + 10240 + wr1 * 80 + wq1 * 16, g_wl + wrow_b + (KC) + wq1 * 8, 16);\
        cpa16(s0 + 20480 + wr0 * 80 + wq0 * 16, xh + xrow0 + (KC) + wq0 * 8, sz0);  \
        cpa16(s0 + 20480 + wr1 * 80 + wq1 * 16, xh + xrow1 + (KC) + wq1 * 8, sz1);  \
        if (!IS_PROJ) {                                                             \
            cpa16(s0 + 30720 + wr0 * 80 + wq0 * 16, g_xl + xrow0 + (KC) + wq0 * 8, sz0); \
            cpa16(s0 + 30720 + wr1 * 80 + wq1 * 16, g_xl + xrow1 + (KC) + wq1 * 8, sz1); \
        }                                                                           \
        asm volatile("cp.async.commit_group;");                                     \
    } while (0)

    STAGE_LOAD(0, 0);

#pragma unroll 1
    for (int i = 0; i < 16; i++) {
        if (i + 1 < 16) {
            STAGE_LOAD((i + 1) & 1, (i + 1) * 32);
            asm volatile("cp.async.wait_group 1;");
        } else {
            asm volatile("cp.async.wait_group 0;");
        }
        __syncthreads();
        const uint32_t st = sb + (i & 1) * STAGE_B;
        const uint32_t s_wh = st, s_wl = st + 10240;
        const uint32_t s_xh = st + 20480 + wt * 2560;
        const uint32_t s_xl = st + 30720 + wt * 2560;
#pragma unroll
        for (int kk = 0; kk < 32; kk += 16) {
            uint32_t Ah[4][4], Bh[4][2];
#pragma unroll
            for (int ot = 0; ot < 4; ot++)
                ldsm4(s_wh + ((oh * 64 + ot * 16 + aRow) * 40 + kk + aK) * 2, Ah[ot]);
#pragma unroll
            for (int n2 = 0; n2 < 2; n2++) {
                uint32_t d[4];
                ldsm4(s_xh + ((n2 * 16 + bRow) * 40 + kk + bK) * 2, d);
                Bh[n2 * 2][0] = d[0]; Bh[n2 * 2][1] = d[1];
                Bh[n2 * 2 + 1][0] = d[2]; Bh[n2 * 2 + 1][1] = d[3];
            }
#pragma unroll
            for (int ot = 0; ot < 4; ot++)
#pragma unroll
                for (int nt = 0; nt < 4; nt++) mma_bf16(acc[ot][nt], Ah[ot], Bh[nt]);
            if (!IS_PROJ) {
                uint32_t Bl[4][2];
#pragma unroll
                for (int n2 = 0; n2 < 2; n2++) {
                    uint32_t d[4];
                    ldsm4(s_xl + ((n2 * 16 + bRow) * 40 + kk + bK) * 2, d);
                    Bl[n2 * 2][0] = d[0]; Bl[n2 * 2][1] = d[1];
                    Bl[n2 * 2 + 1][0] = d[2]; Bl[n2 * 2 + 1][1] = d[3];
                }
#pragma unroll
                for (int ot = 0; ot < 4; ot++)
#pragma unroll
                    for (int nt = 0; nt < 4; nt++) mma_bf16(acc[ot][nt], Ah[ot], Bl[nt]);
            }
            uint32_t Al[4][4];
#pragma unroll
            for (int ot = 0; ot < 4; ot++)
                ldsm4(s_wl + ((oh * 64 + ot * 16 + aRow) * 40 + kk + aK) * 2, Al[ot]);
#pragma unroll
            for (int ot = 0; ot < 4; ot++)
#pragma unroll
                for (int nt = 0; nt < 4; nt++) mma_bf16(acc[ot][nt], Al[ot], Bh[nt]);
        }
        __syncthreads();
    }

    // Epilogue: two o-half passes through shared, BN + LIF + borderline flag
    float* ys = (float*)SM;    // [4t][64o][33]
    const int cg = lane >> 2, ctg = lane & 3;
#pragma unroll 1
    for (int pass = 0; pass < 2; pass++) {
        if (oh == pass) {
#pragma unroll
            for (int ot = 0; ot < 4; ot++)
#pragma unroll
                for (int nt = 0; nt < 4; nt++) {
                    int row = ot * 16 + cg, col = nt * 8 + ctg * 2;
                    ys[(wt * 64 + row) * 33 + col]         = acc[ot][nt][0];
                    ys[(wt * 64 + row) * 33 + col + 1]     = acc[ot][nt][1];
                    ys[(wt * 64 + row + 8) * 33 + col]     = acc[ot][nt][2];
                    ys[(wt * 64 + row + 8) * 33 + col + 1] = acc[ot][nt][3];
                }
        }
        __syncthreads();
        {
            const int o_loc = tid >> 2, nq = tid & 3;
            const int og = o128 + pass * 64 + o_loc;
            const int br = IS_PROJ ? 3 : (og >> 9);
            const int o_in = IS_PROJ ? og : (og & 511);
            const float inv = g_inv[br * 512 + o_in], shf = g_shift[br * 512 + o_in];
#pragma unroll
            for (int j = 0; j < 8; j++) {
                int nl = nq * 8 + j, gn = n0 + nl;
                if (gn < 196) {
                    float v = 0.f;
                    bool bad = false;
                    float fs[4];
#pragma unroll
                    for (int t = 0; t < 4; t++) {
                        float y = fmaf(ys[(t * 64 + o_loc) * 33 + nl], inv, shf);
                        v += (y - v) * 0.5f;
                        float d = v - 1.0f;
                        if (fabsf(d) < MARGIN_) bad = true;
                        bool s = d >= 0.f;
                        fs[t] = s ? 1.f : 0.f;
                        if (s) v = 0.f;
                    }
                    if (IS_PROJ) {
#pragma unroll
                        for (int t = 0; t < 4; t++)
                            o_out[((size_t)(t * 64 + b) * 512 + o_in) * 196 + gn] = fs[t];
                    } else {
#pragma unroll
                        for (int t = 0; t < 4; t++)
                            g_spk[((((size_t)br * 4 + t) * 64 + b) * 512 + o_in) * 196 + gn] =
                                (unsigned char)(fs[t] != 0.f);
                    }
                    if (bad) {
                        if (IS_PROJ) {
                            int s = atomicAdd(&g_cnt[1], 1);
                            if (s < CAP1)
                                g_fix1[s] = ((unsigned)b << 17) | ((unsigned)o_in << 8) | gn;
                        } else {
                            int s = atomicAdd(&g_cnt[0], 1);
                            if (s < CAP0)
                                g_fix0[s] = ((unsigned)br << 23) | ((unsigned)b << 17) |
                                            ((unsigned)o_in << 8) | gn;
                        }
                    }
                }
            }
        }
        __syncthreads();
    }
#undef STAGE_LOAD
}

// ---------------------------------------------------------------------------
// Fixup: exact fp32 recompute, STRICT sequential c=0..511 order (reference-
// matching). QKV reads fp32 g_xT; proj reads bf16 g_s2h (0/1 -> exact f32).
// ---------------------------------------------------------------------------
template<int IS_PROJ>
__global__ void fixup(const float* __restrict__ w, float* __restrict__ o_out) {
    int cnt = g_cnt[IS_PROJ];
    int cap = IS_PROJ ? CAP1 : CAP0;
    if (cnt > cap) cnt = cap;
    for (int e = blockIdx.x * blockDim.x + threadIdx.x; e < cnt;
         e += gridDim.x * blockDim.x) {
        unsigned u = IS_PROJ ? g_fix1[e] : g_fix0[e];
        int n = u & 255, o = (u >> 8) & 511, bb = (u >> 17) & 63;
        int br = IS_PROJ ? 3 : (int)(u >> 23);
        const float* wr = w + ((size_t)br * 512 + o) * 512;
        float inv = g_inv[br * 512 + o], shf = g_shift[br * 512 + o];
        float v = 0.f;
#pragma unroll 1
        for (int t = 0; t < 4; t++) {
            float s = 0.f;
            if (IS_PROJ) {
                const __nv_bfloat16* xr = g_s2h + ((size_t)((t * 64 + bb) * 196 + n)) * 512;
#pragma unroll 4
                for (int c = 0; c < 512; c += 2) {
                    __nv_bfloat162 p = *(const __nv_bfloat162*)(xr + c);
                    s = fmaf(wr[c],     __low2float(p),  s);
                    s = fmaf(wr[c + 1], __high2float(p), s);
                }
            } else {
                const float* xr = g_xT + ((size_t)((t * 64 + bb) * 196 + n)) * 512;
#pragma unroll 4
                for (int c = 0; c < 512; c += 4) {
                    float4 a  = *(const float4*)(wr + c);
                    float4 xv = *(const float4*)(xr + c);
                    s = fmaf(a.x, xv.x, s);
                    s = fmaf(a.y, xv.y, s);
                    s = fmaf(a.z, xv.z, s);
                    s = fmaf(a.w, xv.w, s);
                }
            }
            float y = fmaf(s, inv, shf);
            v += (y - v) * 0.5f;
            bool sp = (v - 1.0f) >= 0.f;
            if (IS_PROJ)
                o_out[((size_t)(t * 64 + bb) * 512 + o) * 196 + n] = sp ? 1.f : 0.f;
            else
                g_spk[((((size_t)br * 4 + t) * 64 + bb) * 512 + o) * 196 + n] = sp ? 1 : 0;
            if (sp) v = 0.f;
        }
    }
}

// ---------------------------------------------------------------------------
__global__ void pack_bits() {
    int idx = blockIdx.x * 256 + threadIdx.x;
    if (idx >= (int)BITS_SZ) return;
    int n = idx % 196; int r = idx / 196;
    int h = r & 7;  r >>= 3;
    int b = r & 63; r >>= 6;
    int t = r & 3;  int br = r >> 2;
    const unsigned char* base = g_spk +
        ((((size_t)br * 4 + t) * 64 + b) * 512 + h * 64) * 196 + n;
    unsigned long long w = 0ull;
#pragma unroll
    for (int d = 0; d < 64; d++)
        w |= (unsigned long long)(base[(size_t)d * 196] & 1) << d;
    g_bits[idx] = w;
}

// ---------------------------------------------------------------------------
// Attention per (b,h), all 4 t in-block. Exact integer popcount math.
// ---------------------------------------------------------------------------
__global__ __launch_bounds__(512) void attn_kernel(float* __restrict__ attn_out) {
    const int bh = blockIdx.x;
    const int b = bh >> 3, h = bh & 7;

    __shared__ unsigned long long sq[200], sk[200], sv[200];
    __shared__ unsigned long long kcol[64][4], vcol[64][4];
    __shared__ unsigned short s_cnt[4096];
    __shared__ unsigned char  s_spk[64 * 212];

    const int tid = threadIdx.x;
    const int d = tid & 63, g = tid >> 6;

    float vst[25];
#pragma unroll
    for (int j = 0; j < 25; j++) vst[j] = 0.f;

    for (int t = 0; t < 4; t++) {
        size_t qidx = ((size_t)(t * 64 + b) * 8 + h) * 196;
        for (int i = tid; i < 600; i += 512) {
            if (i < 196)      sq[i]       = g_bits[qidx + i];
            else if (i < 392) sk[i - 196] = g_bits[BR_BITS + qidx + (i - 196)];
            else if (i < 588) sv[i - 392] = g_bits[2 * BR_BITS + qidx + (i - 392)];
            else {
                int j = i - 588;
                if (j < 4)      sq[196 + j] = 0ull;
                else if (j < 8) sk[192 + j] = 0ull;
                else            sv[188 + j] = 0ull;
            }
        }
        __syncthreads();
        {
            int e = tid & 63, wd = (tid >> 6) & 3, sel = tid >> 8;
            const unsigned long long* src = sel ? sv : sk;
            int m0 = wd * 64;
            int m1 = m0 + 64 < 196 ? m0 + 64 : 196;
            unsigned long long a = 0ull;
            for (int m = m0; m < m1; m++)
                a |= ((src[m] >> e) & 1ull) << (m - m0);
            if (sel) vcol[e][wd] = a; else kcol[e][wd] = a;
        }
        __syncthreads();
        size_t abase = ((size_t)(t * 64 + b) * 8 + h) * 38416;
        for (int i = tid; i < 38416; i += 512) {
            int n = i / 196; int m = i - n * 196;
            attn_out[abase + i] = (float)__popcll(sq[n] & sk[m]) * 0.125f;
        }
        for (int i = tid; i < 4096; i += 512) {
            int e = i >> 6, dd = i & 63;
            int s = __popcll(kcol[e][0] & vcol[dd][0]) + __popcll(kcol[e][1] & vcol[dd][1])
                  + __popcll(kcol[e][2] & vcol[dd][2]) + __popcll(kcol[e][3] & vcol[dd][3]);
            s_cnt[i] = (unsigned short)s;
        }
        __syncthreads();
#pragma unroll 1
        for (int j = 0; j < 25; j++) {
            int n = g + 8 * j;
            if (n < 196) {
                unsigned long long q = sq[n];
                int sum = 0;
                while (q) {
                    int e = __ffsll((long long)q) - 1;
                    q &= q - 1;
                    sum += s_cnt[(e << 6) + d];
                }
                float o1 = (float)sum * 0.125f;
                float vv = vst[j];
                vv += (o1 - vv) * 0.5f;
                bool s = (vv >= 0.5f);
                vst[j] = s ? 0.f : vv;
                s_spk[d * 212 + n] = s ? 1 : 0;
            }
        }
        __syncthreads();
        // flush spikes as bf16 (exact), layout [t,b,n,c] for the proj GEMM
        for (int i = tid; i < 196 * 64; i += 512) {
            int n = i >> 6, dd = i & 63;
            g_s2h[((size_t)((t * 64 + b) * 196 + n)) * 512 + h * 64 + dd] =
                __float2bfloat16((float)s_spk[dd * 212 + n]);
        }
        __syncthreads();
    }
}

// ---------------------------------------------------------------------------
extern "C" void kernel_launch(void* const* d_in, const int* in_sizes, int n_in,
                              void* d_out, int out_size) {
    const float* x     = (const float*)d_in[0];
    const float* w     = (const float*)d_in[2];
    const float* gamma = (const float*)d_in[3];
    const float* beta  = (const float*)d_in[4];
    const float* mean  = (const float*)d_in[5];
    const float* var   = (const float*)d_in[6];

    float* o_out    = (float*)d_out;
    float* attn_out = o_out + O_ELEMS;

    const int SMEM = 2 * STAGE_B;   // 81920
    cudaFuncSetAttribute(mma_gemm_lif<0>, cudaFuncAttributeMaxDynamicSharedMemorySize, SMEM);
    cudaFuncSetAttribute(mma_gemm_lif<1>, cudaFuncAttributeMaxDynamicSharedMemorySize, SMEM);

    prep_bn<<<8, 256>>>(gamma, beta, mean, var);              // 1 (also zeroes g_cnt)
    w_split<<<4096, 256>>>(w);                                // 2
    x_split<<<dim3(16, 7, 256), dim3(32, 8)>>>(x);            // 3
    mma_gemm_lif<0><<<dim3(7, 12, 64), 256, SMEM>>>(nullptr); // 4 <- ncu captures this
    fixup<0><<<256, 256>>>(w, nullptr);
    pack_bits<<<4704, 256>>>();
    attn_kernel<<<512, 512>>>(attn_out);
    mma_gemm_lif<1><<<dim3(7, 4, 64), 256, SMEM>>>(o_out);
    fixup<1><<<64, 256>>>(w, o_out);
}

// round 8
// speedup vs baseline: 1.9794x; 1.0288x over previous
#include <cuda_runtime.h>
#include <cuda_bf16.h>
#include <cstdint>

// T=4, B=64, C=512, N=196, H=8, D=64
#define EPS_    1e-5f
#define MARGIN_ 5e-4f

constexpr size_t BITS_SZ = 3ULL * 4 * 64 * 8 * 196;     // packed u64
constexpr size_t BR_BITS = 4ULL * 64 * 8 * 196;
constexpr size_t O_ELEMS = 4ULL * 64 * 512 * 196;
constexpr size_t XT_SZ   = 4ULL * 64 * 196 * 512;       // [t,b,n,c]
constexpr int CAP0 = 1 << 20;
constexpr int CAP1 = 1 << 18;
constexpr int STG    = 40960;            // bytes/stage: Wh|Wl|Xh|Xl @ 10240 each
constexpr int NSTAGE = 4;
constexpr int SMEMSZ = NSTAGE * STG;     // 163840

__device__ __align__(16) unsigned long long g_bits[BITS_SZ];
__device__ __align__(16) float              g_xT[XT_SZ];     // fp32 (fixup only)
__device__ __align__(16) __nv_bfloat16      g_xh[XT_SZ];
__device__ __align__(16) __nv_bfloat16      g_xl[XT_SZ];
__device__ __align__(16) __nv_bfloat16      g_s2h[XT_SZ];    // attn_lif spikes bf16
__device__ __align__(16) __nv_bfloat16      g_wh[2048 * 512];
__device__ __align__(16) __nv_bfloat16      g_wl[2048 * 512];
__device__ float    g_inv[2048];
__device__ float    g_shift[2048];
__device__ unsigned g_fix0[CAP0];
__device__ unsigned g_fix1[CAP1];
__device__ int      g_cnt[2];

// ---------------------------------------------------------------------------
__global__ void prep_bn(const float* __restrict__ gamma, const float* __restrict__ beta,
                        const float* __restrict__ mean,  const float* __restrict__ var) {
    int i = blockIdx.x * 256 + threadIdx.x;
    if (blockIdx.x == 0 && threadIdx.x < 2) g_cnt[threadIdx.x] = 0;
    if (i < 2048) {
        float inv = gamma[i] * rsqrtf(var[i] + EPS_);
        g_inv[i]   = inv;
        g_shift[i] = beta[i] - mean[i] * inv;
    }
}

__global__ void w_split(const float* __restrict__ w) {
    int i = blockIdx.x * 256 + threadIdx.x;
    float f = w[i];
    __nv_bfloat16 h = __float2bfloat16(f);
    g_wh[i] = h;
    g_wl[i] = __float2bfloat16(f - __bfloat162float(h));
}

// x [t,b,c,n] -> g_xT f32 + g_xh/g_xl bf16, all [t,b,n,c]
__global__ void x_split(const float* __restrict__ x) {
    __shared__ float tile[32][33];
    int tb = blockIdx.z;
    int c0 = blockIdx.x * 32, n0 = blockIdx.y * 32;
#pragma unroll
    for (int i = 0; i < 4; i++) {
        int c = threadIdx.y + i * 8, n = threadIdx.x;
        float v = (n0 + n < 196) ? x[((size_t)tb * 512 + c0 + c) * 196 + n0 + n] : 0.f;
        tile[c][n] = v;
    }
    __syncthreads();
#pragma unroll
    for (int i = 0; i < 4; i++) {
        int n = threadIdx.y + i * 8, c = threadIdx.x;
        if (n0 + n < 196) {
            size_t idx = ((size_t)tb * 196 + n0 + n) * 512 + c0 + c;
            float v = tile[c][n];
            __nv_bfloat16 h = __float2bfloat16(v);
            g_xT[idx] = v;
            g_xh[idx] = h;
            g_xl[idx] = __float2bfloat16(v - __bfloat162float(h));
        }
    }
}

// ---------------------------------------------------------------------------
__device__ __forceinline__ void ldsm4(uint32_t addr, uint32_t* d) {
    asm volatile("ldmatrix.sync.aligned.m8n8.x4.shared.b16 {%0,%1,%2,%3}, [%4];"
        : "=r"(d[0]), "=r"(d[1]), "=r"(d[2]), "=r"(d[3]) : "r"(addr));
}
__device__ __forceinline__ void mma_bf16(float* c, const uint32_t* a, const uint32_t* b) {
    asm volatile(
        "mma.sync.aligned.m16n8k16.row.col.f32.bf16.bf16.f32 "
        "{%0,%1,%2,%3}, {%4,%5,%6,%7}, {%8,%9}, {%0,%1,%2,%3};"
        : "+f"(c[0]), "+f"(c[1]), "+f"(c[2]), "+f"(c[3])
        : "r"(a[0]), "r"(a[1]), "r"(a[2]), "r"(a[3]), "r"(b[0]), "r"(b[1]));
}
__device__ __forceinline__ void cpa16(uint32_t dst, const void* src) {
    asm volatile("cp.async.cg.shared.global [%0], [%1], 16;" :: "r"(dst), "l"(src));
}

// One stage: thread tid stages chunk (row=tid>>2, q=tid&3) of each region.
template<int IS_PROJ>
__device__ __forceinline__ void stage_load(uint32_t sbase, int kc, int wrow0, int b, int n0) {
    const int tid = threadIdx.x;
    const int row = tid >> 2, q = tid & 3;
    const uint32_t doff = (uint32_t)(row * 80 + q * 16);
    const __nv_bfloat16* __restrict__ xs = IS_PROJ ? g_s2h : g_xh;
    cpa16(sbase + doff,         g_wh + (size_t)(wrow0 + row) * 512 + kc + q * 8);
    cpa16(sbase + 10240 + doff, g_wl + (size_t)(wrow0 + row) * 512 + kc + q * 8);
    int t = row >> 5, n = row & 31;
    size_t xoff = ((size_t)((t * 64 + b) * 196 + n0 + n)) * 512 + kc + q * 8;
    cpa16(sbase + 20480 + doff, xs + xoff);
    if (!IS_PROJ) cpa16(sbase + 30720 + doff, g_xl + xoff);
    asm volatile("cp.async.commit_group;");
}

// ---------------------------------------------------------------------------
// mma.sync GEMM + BN + LIF, 4-stage cp.async. CTA tile 128o x 32n x 4t,
// 512 thr / 16 warps: warp = (t = w&3, oq = w>>2), warp tile 32o x 32n.
// IS_PROJ=0: 3 split passes, spikes -> g_bits via ballot.
// IS_PROJ=1: 2 passes (X binary exact), f32 spikes -> o_out (coalesced).
// ---------------------------------------------------------------------------
template<int IS_PROJ>
__global__ __launch_bounds__(512, 1) void mma_gemm_lif(float* __restrict__ o_out) {
    extern __shared__ __align__(16) unsigned char SM[];
    const int n0   = min((int)blockIdx.x * 32, 164);   // overlap tile: all n valid
    const int o128 = blockIdx.y << 7;
    const int b    = blockIdx.z;
    const int wrow0 = (IS_PROJ ? 1536 : 0) + o128;
    const int tid = threadIdx.x, lane = tid & 31, warp = tid >> 5;
    const int wt = warp & 3, oq = warp >> 2;
    const uint32_t sb = (uint32_t)__cvta_generic_to_shared(SM);

    float acc[2][4][4];
#pragma unroll
    for (int a = 0; a < 2; a++)
#pragma unroll
        for (int c = 0; c < 4; c++)
#pragma unroll
            for (int d = 0; d < 4; d++) acc[a][c][d] = 0.f;

    const int aRow = lane & 15,                aK = (lane >> 4) << 3;
    const int bRow = (lane & 7) | ((lane >> 4) << 3), bK = ((lane >> 3) & 1) << 3;

    stage_load<IS_PROJ>(sb,           0, wrow0, b, n0);
    stage_load<IS_PROJ>(sb + STG,    32, wrow0, b, n0);
    stage_load<IS_PROJ>(sb + 2*STG,  64, wrow0, b, n0);

#pragma unroll 1
    for (int i = 0; i < 16; i++) {
        if (i <= 13)      asm volatile("cp.async.wait_group 2;");
        else if (i == 14) asm volatile("cp.async.wait_group 1;");
        else              asm volatile("cp.async.wait_group 0;");
        __syncthreads();
        if (i + 3 < 16)
            stage_load<IS_PROJ>(sb + ((i + 3) & 3) * STG, (i + 3) * 32, wrow0, b, n0);

        const uint32_t st = sb + (i & 3) * STG;
        const uint32_t s_wh = st, s_wl = st + 10240;
        const uint32_t s_xh = st + 20480 + wt * 2560;
        const uint32_t s_xl = st + 30720 + wt * 2560;
#pragma unroll
        for (int kk = 0; kk < 32; kk += 16) {
            uint32_t Ah[2][4], Bh[4][2];
#pragma unroll
            for (int ot = 0; ot < 2; ot++)
                ldsm4(s_wh + ((oq * 32 + ot * 16 + aRow) * 40 + kk + aK) * 2, Ah[ot]);
#pragma unroll
            for (int n2 = 0; n2 < 2; n2++) {
                uint32_t d[4];
                ldsm4(s_xh + ((n2 * 16 + bRow) * 40 + kk + bK) * 2, d);
                Bh[n2 * 2][0] = d[0]; Bh[n2 * 2][1] = d[1];
                Bh[n2 * 2 + 1][0] = d[2]; Bh[n2 * 2 + 1][1] = d[3];
            }
#pragma unroll
            for (int ot = 0; ot < 2; ot++)
#pragma unroll
                for (int nt = 0; nt < 4; nt++) mma_bf16(acc[ot][nt], Ah[ot], Bh[nt]);
            if (!IS_PROJ) {
                uint32_t Bl[4][2];
#pragma unroll
                for (int n2 = 0; n2 < 2; n2++) {
                    uint32_t d[4];
                    ldsm4(s_xl + ((n2 * 16 + bRow) * 40 + kk + bK) * 2, d);
                    Bl[n2 * 2][0] = d[0]; Bl[n2 * 2][1] = d[1];
                    Bl[n2 * 2 + 1][0] = d[2]; Bl[n2 * 2 + 1][1] = d[3];
                }
#pragma unroll
                for (int ot = 0; ot < 2; ot++)
#pragma unroll
                    for (int nt = 0; nt < 4; nt++) mma_bf16(acc[ot][nt], Ah[ot], Bl[nt]);
            }
            uint32_t Al[2][4];
#pragma unroll
            for (int ot = 0; ot < 2; ot++)
                ldsm4(s_wl + ((oq * 32 + ot * 16 + aRow) * 40 + kk + aK) * 2, Al[ot]);
#pragma unroll
            for (int ot = 0; ot < 2; ot++)
#pragma unroll
                for (int nt = 0; nt < 4; nt++) mma_bf16(acc[ot][nt], Al[ot], Bh[nt]);
        }
    }

    // ---- epilogue: acc -> ys[4t][128o][33] (smem), then BN + LIF
    __syncthreads();
    float* ys = (float*)SM;
    {
        const int cg = lane >> 2, ctg = lane & 3;
#pragma unroll
        for (int ot = 0; ot < 2; ot++)
#pragma unroll
            for (int nt = 0; nt < 4; nt++) {
                int row = oq * 32 + ot * 16 + cg, col = nt * 8 + ctg * 2;
                ys[(wt * 128 + row) * 33 + col]         = acc[ot][nt][0];
                ys[(wt * 128 + row) * 33 + col + 1]     = acc[ot][nt][1];
                ys[(wt * 128 + row + 8) * 33 + col]     = acc[ot][nt][2];
                ys[(wt * 128 + row + 8) * 33 + col + 1] = acc[ot][nt][3];
            }
    }
    __syncthreads();

    if (!IS_PROJ) {
        // warp = (oq2 = warp&3 -> 32 o lanes, ng = warp>>2 -> 8 n each)
        const int oq2 = warp & 3, ng = warp >> 2;
        const int o_loc = oq2 * 32 + lane;
        const int og = o128 + o_loc;
        const int br = og >> 9, o_in = og & 511;
        const float inv = g_inv[br * 512 + o_in], shf = g_shift[br * 512 + o_in];
        const int h = (o_in >> 6) & 7, half = (o_loc >> 5) & 1;
#pragma unroll
        for (int j = 0; j < 8; j++) {
            const int nl = ng * 8 + j, n = n0 + nl;
            float v = 0.f;
            bool bad = false, sp[4];
#pragma unroll
            for (int t = 0; t < 4; t++) {
                float y = fmaf(ys[(t * 128 + o_loc) * 33 + nl], inv, shf);
                v += (y - v) * 0.5f;
                float d = v - 1.0f;
                if (fabsf(d) < MARGIN_) bad = true;
                sp[t] = d >= 0.f;
                if (sp[t]) v = 0.f;
            }
#pragma unroll
            for (int t = 0; t < 4; t++) {
                uint32_t m = __ballot_sync(0xffffffffu, sp[t]);
                if (lane == 0)
                    ((uint32_t*)g_bits)[((((size_t)br * 4 + t) * 64 + b) * 8 + h) * 392
                                        + n * 2 + half] = m;
            }
            if (bad) {
                int s = atomicAdd(&g_cnt[0], 1);
                if (s < CAP0)
                    g_fix0[s] = ((unsigned)br << 23) | ((unsigned)b << 17) |
                                ((unsigned)o_in << 8) | n;
            }
        }
    } else {
        // warp -> 8 o rows, lane -> n (coalesced stores)
        const int n = n0 + lane;
#pragma unroll
        for (int j = 0; j < 8; j++) {
            const int o_in = o128 + warp * 8 + j;
            const float inv = g_inv[1536 + o_in], shf = g_shift[1536 + o_in];
            float v = 0.f;
            bool bad = false;
#pragma unroll
            for (int t = 0; t < 4; t++) {
                float y = fmaf(ys[(t * 128 + warp * 8 + j) * 33 + lane], inv, shf);
                v += (y - v) * 0.5f;
                float d = v - 1.0f;
                if (fabsf(d) < MARGIN_) bad = true;
                bool s = d >= 0.f;
                o_out[((size_t)(t * 64 + b) * 512 + o_in) * 196 + n] = s ? 1.f : 0.f;
                if (s) v = 0.f;
            }
            if (bad) {
                int s = atomicAdd(&g_cnt[1], 1);
                if (s < CAP1)
                    g_fix1[s] = ((unsigned)b << 17) | ((unsigned)o_in << 8) | n;
            }
        }
    }
}

// ---------------------------------------------------------------------------
// Fixup: exact fp32 recompute, STRICT sequential c=0..511 order (reference-
// matching). QKV patches g_bits bitwise; proj patches o_out.
// ---------------------------------------------------------------------------
template<int IS_PROJ>
__global__ void fixup(const float* __restrict__ w, float* __restrict__ o_out) {
    int cnt = g_cnt[IS_PROJ];
    int cap = IS_PROJ ? CAP1 : CAP0;
    if (cnt > cap) cnt = cap;
    for (int e = blockIdx.x * blockDim.x + threadIdx.x; e < cnt;
         e += gridDim.x * blockDim.x) {
        unsigned u = IS_PROJ ? g_fix1[e] : g_fix0[e];
        int n = u & 255, o = (u >> 8) & 511, bb = (u >> 17) & 63;
        int br = IS_PROJ ? 3 : (int)(u >> 23);
        const float* wr = w + ((size_t)br * 512 + o) * 512;
        float inv = g_inv[br * 512 + o], shf = g_shift[br * 512 + o];
        float v = 0.f;
#pragma unroll 1
        for (int t = 0; t < 4; t++) {
            float s = 0.f;
            if (IS_PROJ) {
                const __nv_bfloat16* xr = g_s2h + ((size_t)((t * 64 + bb) * 196 + n)) * 512;
#pragma unroll 4
                for (int c = 0; c < 512; c += 2) {
                    __nv_bfloat162 p = *(const __nv_bfloat162*)(xr + c);
                    s = fmaf(wr[c],     __low2float(p),  s);
                    s = fmaf(wr[c + 1], __high2float(p), s);
                }
            } else {
                const float* xr = g_xT + ((size_t)((t * 64 + bb) * 196 + n)) * 512;
#pragma unroll 4
                for (int c = 0; c < 512; c += 4) {
                    float4 a  = *(const float4*)(wr + c);
                    float4 xv = *(const float4*)(xr + c);
                    s = fmaf(a.x, xv.x, s);
                    s = fmaf(a.y, xv.y, s);
                    s = fmaf(a.z, xv.z, s);
                    s = fmaf(a.w, xv.w, s);
                }
            }
            float y = fmaf(s, inv, shf);
            v += (y - v) * 0.5f;
            bool sp = (v - 1.0f) >= 0.f;
            if (IS_PROJ) {
                o_out[((size_t)(t * 64 + bb) * 512 + o) * 196 + n] = sp ? 1.f : 0.f;
            } else {
                int h = o >> 6, d = o & 63;
                uint32_t* wp = ((uint32_t*)g_bits) +
                    ((((size_t)br * 4 + t) * 64 + bb) * 8 + h) * 392 + n * 2 + (d >> 5);
                uint32_t m = 1u << (d & 31);
                if (sp) atomicOr(wp, m); else atomicAnd(wp, ~m);
            }
            if (sp) v = 0.f;
        }
    }
}

// ---------------------------------------------------------------------------
// Attention per (b,h), all 4 t in-block. Exact integer popcount math.
// ---------------------------------------------------------------------------
__global__ __launch_bounds__(512) void attn_kernel(float* __restrict__ attn_out) {
    const int bh = blockIdx.x;
    const int b = bh >> 3, h = bh & 7;

    __shared__ unsigned long long sq[200], sk[200], sv[200];
    __shared__ unsigned long long kcol[64][4], vcol[64][4];
    __shared__ unsigned short s_cnt[4096];
    __shared__ unsigned char  s_spk[64 * 212];

    const int tid = threadIdx.x;
    const int d = tid & 63, g = tid >> 6;

    float vst[25];
#pragma unroll
    for (int j = 0; j < 25; j++) vst[j] = 0.f;

    for (int t = 0; t < 4; t++) {
        size_t qidx = ((size_t)(t * 64 + b) * 8 + h) * 196;
        for (int i = tid; i < 600; i += 512) {
            if (i < 196)      sq[i]       = g_bits[qidx + i];
            else if (i < 392) sk[i - 196] = g_bits[BR_BITS + qidx + (i - 196)];
            else if (i < 588) sv[i - 392] = g_bits[2 * BR_BITS + qidx + (i - 392)];
            else {
                int j = i - 588;
                if (j < 4)      sq[196 + j] = 0ull;
                else if (j < 8) sk[192 + j] = 0ull;
                else            sv[188 + j] = 0ull;
            }
        }
        __syncthreads();
        {
            int e = tid & 63, wd = (tid >> 6) & 3, sel = tid >> 8;
            const unsigned long long* src = sel ? sv : sk;
            int m0 = wd * 64;
            int m1 = m0 + 64 < 196 ? m0 + 64 : 196;
            unsigned long long a = 0ull;
            for (int m = m0; m < m1; m++)
                a |= ((src[m] >> e) & 1ull) << (m - m0);
            if (sel) vcol[e][wd] = a; else kcol[e][wd] = a;
        }
        __syncthreads();
        size_t abase = ((size_t)(t * 64 + b) * 8 + h) * 38416;
        for (int i = tid; i < 38416; i += 512) {
            int n = i / 196; int m = i - n * 196;
            attn_out[abase + i] = (float)__popcll(sq[n] & sk[m]) * 0.125f;
        }
        for (int i = tid; i < 4096; i += 512) {
            int e = i >> 6, dd = i & 63;
            int s = __popcll(kcol[e][0] & vcol[dd][0]) + __popcll(kcol[e][1] & vcol[dd][1])
                  + __popcll(kcol[e][2] & vcol[dd][2]) + __popcll(kcol[e][3] & vcol[dd][3]);
            s_cnt[i] = (unsigned short)s;
        }
        __syncthreads();
#pragma unroll 1
        for (int j = 0; j < 25; j++) {
            int n = g + 8 * j;
            if (n < 196) {
                unsigned long long q = sq[n];
                int sum = 0;
                while (q) {
                    int e = __ffsll((long long)q) - 1;
                    q &= q - 1;
                    sum += s_cnt[(e << 6) + d];
                }
                float o1 = (float)sum * 0.125f;
                float vv = vst[j];
                vv += (o1 - vv) * 0.5f;
                bool s = (vv >= 0.5f);
                vst[j] = s ? 0.f : vv;
                s_spk[d * 212 + n] = s ? 1 : 0;
            }
        }
        __syncthreads();
        // flush spikes as bf16 (exact), layout [t,b,n,c] for the proj GEMM
        for (int i = tid; i < 196 * 64; i += 512) {
            int n = i >> 6, dd = i & 63;
            g_s2h[((size_t)((t * 64 + b) * 196 + n)) * 512 + h * 64 + dd] =
                __float2bfloat16((float)s_spk[dd * 212 + n]);
        }
        __syncthreads();
    }
}

// ---------------------------------------------------------------------------
extern "C" void kernel_launch(void* const* d_in, const int* in_sizes, int n_in,
                              void* d_out, int out_size) {
    const float* x     = (const float*)d_in[0];
    const float* w     = (const float*)d_in[2];
    const float* gamma = (const float*)d_in[3];
    const float* beta  = (const float*)d_in[4];
    const float* mean  = (const float*)d_in[5];
    const float* var   = (const float*)d_in[6];

    float* o_out    = (float*)d_out;
    float* attn_out = o_out + O_ELEMS;

    cudaFuncSetAttribute(mma_gemm_lif<0>, cudaFuncAttributeMaxDynamicSharedMemorySize, SMEMSZ);
    cudaFuncSetAttribute(mma_gemm_lif<1>, cudaFuncAttributeMaxDynamicSharedMemorySize, SMEMSZ);

    prep_bn<<<8, 256>>>(gamma, beta, mean, var);                // 1 (zeroes g_cnt)
    w_split<<<4096, 256>>>(w);                                  // 2
    x_split<<<dim3(16, 7, 256), dim3(32, 8)>>>(x);              // 3
    mma_gemm_lif<0><<<dim3(7, 12, 64), 512, SMEMSZ>>>(nullptr); // 4 <- ncu captures this
    fixup<0><<<256, 256>>>(w, nullptr);
    attn_kernel<<<512, 512>>>(attn_out);
    mma_gemm_lif<1><<<dim3(7, 4, 64), 512, SMEMSZ>>>(o_out);
    fixup<1><<<64, 256>>>(w, o_out);
}

// round 9
// speedup vs baseline: 2.2415x; 1.1325x over previous
#include <cuda_runtime.h>
#include <cuda_bf16.h>
#include <cstdint>

// T=4, B=64, C=512, N=196, H=8, D=64
#define EPS_    1e-5f
#define MARGIN_ 5e-4f

constexpr size_t BITS_SZ = 3ULL * 4 * 64 * 8 * 196;     // packed u64
constexpr size_t BR_BITS = 4ULL * 64 * 8 * 196;
constexpr size_t O_ELEMS = 4ULL * 64 * 512 * 196;
constexpr size_t XT_SZ   = 4ULL * 64 * 196 * 512;       // [t,b,n,c]
constexpr int CAP0 = 1 << 20;
constexpr int CAP1 = 1 << 18;
constexpr int STG    = 32768;            // stage: Wh|Wl|Xh|Xl @ 8192 each, 64B pitch
constexpr int SMEMSZ = 3 * STG;          // 98304 -> 2 CTAs/SM

__device__ __align__(16) unsigned long long g_bits[BITS_SZ];
__device__ __align__(16) float              g_xT[XT_SZ];     // fp32 (fixup only)
__device__ __align__(16) __nv_bfloat16      g_xh[XT_SZ];
__device__ __align__(16) __nv_bfloat16      g_xl[XT_SZ];
__device__ __align__(16) __nv_bfloat16      g_s2h[XT_SZ];    // attn_lif spikes bf16
__device__ __align__(16) __nv_bfloat16      g_wh[2048 * 512];
__device__ __align__(16) __nv_bfloat16      g_wl[2048 * 512];
__device__ float    g_inv[2048];
__device__ float    g_shift[2048];
__device__ unsigned g_fix0[CAP0];
__device__ unsigned g_fix1[CAP1];
__device__ int      g_cnt[2];

// ---------------------------------------------------------------------------
__global__ void prep_bn(const float* __restrict__ gamma, const float* __restrict__ beta,
                        const float* __restrict__ mean,  const float* __restrict__ var) {
    int i = blockIdx.x * 256 + threadIdx.x;
    if (blockIdx.x == 0 && threadIdx.x < 2) g_cnt[threadIdx.x] = 0;
    if (i < 2048) {
        float inv = gamma[i] * rsqrtf(var[i] + EPS_);
        g_inv[i]   = inv;
        g_shift[i] = beta[i] - mean[i] * inv;
    }
}

__global__ void w_split(const float* __restrict__ w) {
    int i = blockIdx.x * 256 + threadIdx.x;
    float f = w[i];
    __nv_bfloat16 h = __float2bfloat16(f);
    g_wh[i] = h;
    g_wl[i] = __float2bfloat16(f - __bfloat162float(h));
}

// x [t,b,c,n] -> g_xT f32 + g_xh/g_xl bf16, all [t,b,n,c]
__global__ void x_split(const float* __restrict__ x) {
    __shared__ float tile[32][33];
    int tb = blockIdx.z;
    int c0 = blockIdx.x * 32, n0 = blockIdx.y * 32;
#pragma unroll
    for (int i = 0; i < 4; i++) {
        int c = threadIdx.y + i * 8, n = threadIdx.x;
        float v = (n0 + n < 196) ? x[((size_t)tb * 512 + c0 + c) * 196 + n0 + n] : 0.f;
        tile[c][n] = v;
    }
    __syncthreads();
#pragma unroll
    for (int i = 0; i < 4; i++) {
        int n = threadIdx.y + i * 8, c = threadIdx.x;
        if (n0 + n < 196) {
            size_t idx = ((size_t)tb * 196 + n0 + n) * 512 + c0 + c;
            float v = tile[c][n];
            __nv_bfloat16 h = __float2bfloat16(v);
            g_xT[idx] = v;
            g_xh[idx] = h;
            g_xl[idx] = __float2bfloat16(v - __bfloat162float(h));
        }
    }
}

// ---------------------------------------------------------------------------
__device__ __forceinline__ void ldsm4(uint32_t addr, uint32_t* d) {
    asm volatile("ldmatrix.sync.aligned.m8n8.x4.shared.b16 {%0,%1,%2,%3}, [%4];"
        : "=r"(d[0]), "=r"(d[1]), "=r"(d[2]), "=r"(d[3]) : "r"(addr));
}
__device__ __forceinline__ void mma_bf16(float* c, const uint32_t* a, const uint32_t* b) {
    asm volatile(
        "mma.sync.aligned.m16n8k16.row.col.f32.bf16.bf16.f32 "
        "{%0,%1,%2,%3}, {%4,%5,%6,%7}, {%8,%9}, {%0,%1,%2,%3};"
        : "+f"(c[0]), "+f"(c[1]), "+f"(c[2]), "+f"(c[3])
        : "r"(a[0]), "r"(a[1]), "r"(a[2]), "r"(a[3]), "r"(b[0]), "r"(b[1]));
}
__device__ __forceinline__ void cpa16(uint32_t dst, const void* src) {
    asm volatile("cp.async.cg.shared.global [%0], [%1], 16;" :: "r"(dst), "l"(src));
}
// XOR-swizzled address: 64B rows, chunk q permuted by ((row>>1)&3).
// Verified: any 8 consecutive rows at fixed q hit 8 distinct 16B slots.
__device__ __forceinline__ uint32_t sw_addr(uint32_t base, int row, int kElem) {
    int q = kElem >> 3;
    return base + row * 64 + (((q ^ ((row >> 1) & 3)) << 4));
}

// One stage load (256 thr): regions Wh@0, Wl@8192, Xh@16384, Xl@24576.
// Each region = 128 rows x 64B = 512 chunks of 16B; thread does 2 per region.
template<int IS_PROJ>
__device__ __forceinline__ void stage_load(uint32_t sbase, int kc, int wrow0, int b, int n0) {
    const __nv_bfloat16* __restrict__ xs = IS_PROJ ? g_s2h : g_xh;
#pragma unroll
    for (int p = 0; p < 2; p++) {
        int c = threadIdx.x * 2 + p;
        int row = c >> 2, q = c & 3;
        uint32_t doff = (uint32_t)(row * 64 + ((q ^ ((row >> 1) & 3)) << 4));
        cpa16(sbase + doff,        g_wh + (size_t)(wrow0 + row) * 512 + kc + q * 8);
        cpa16(sbase + 8192 + doff, g_wl + (size_t)(wrow0 + row) * 512 + kc + q * 8);
        int t = row >> 5, n = row & 31;
        size_t xoff = ((size_t)((t * 64 + b) * 196 + n0 + n)) * 512 + kc + q * 8;
        cpa16(sbase + 16384 + doff, xs + xoff);
        if (!IS_PROJ) cpa16(sbase + 24576 + doff, g_xl + xoff);
    }
    asm volatile("cp.async.commit_group;");
}

// ---------------------------------------------------------------------------
// mma.sync GEMM + BN + LIF. 3-stage cp.async, 2 CTAs/SM.
// CTA 256 thr / 8 warps: warp = (wt = w&3 -> t, oh = w>>2 -> 64-o half).
// Warp tile 64o x 32n, acc[4][4][4]. 3 passes QKV / 2 passes proj.
// ---------------------------------------------------------------------------
template<int IS_PROJ>
__global__ __launch_bounds__(256, 2) void mma_gemm_lif(float* __restrict__ o_out) {
    extern __shared__ __align__(16) unsigned char SM[];
    const int n0   = min((int)blockIdx.x * 32, 164);   // overlap tile: all n valid
    const int o128 = blockIdx.y << 7;
    const int b    = blockIdx.z;
    const int wrow0 = (IS_PROJ ? 1536 : 0) + o128;
    const int tid = threadIdx.x, lane = tid & 31, warp = tid >> 5;
    const int wt = warp & 3, oh = warp >> 2;
    const uint32_t sb = (uint32_t)__cvta_generic_to_shared(SM);

    float acc[4][4][4];
#pragma unroll
    for (int a = 0; a < 4; a++)
#pragma unroll
        for (int c = 0; c < 4; c++)
#pragma unroll
            for (int d = 0; d < 4; d++) acc[a][c][d] = 0.f;

    const int aRow = lane & 15,                aK = (lane >> 4) << 3;
    const int bRow = (lane & 7) | ((lane >> 4) << 3), bK = ((lane >> 3) & 1) << 3;

    stage_load<IS_PROJ>(sb,            0, wrow0, b, n0);
    stage_load<IS_PROJ>(sb + STG,     32, wrow0, b, n0);

#pragma unroll 1
    for (int i = 0; i < 16; i++) {
        if (i < 15) asm volatile("cp.async.wait_group 1;");
        else        asm volatile("cp.async.wait_group 0;");
        __syncthreads();
        if (i + 2 < 16)
            stage_load<IS_PROJ>(sb + ((i + 2) % 3) * STG, (i + 2) * 32, wrow0, b, n0);

        const uint32_t st  = sb + (i % 3) * STG;
        const uint32_t s_x = st + 16384;
#pragma unroll
        for (int kk = 0; kk < 32; kk += 16) {
            uint32_t A[4][4], B[4][2];
#pragma unroll
            for (int ot = 0; ot < 4; ot++)
                ldsm4(sw_addr(st, oh * 64 + ot * 16 + aRow, kk + aK), A[ot]);
#pragma unroll
            for (int n2 = 0; n2 < 2; n2++) {
                uint32_t d[4];
                ldsm4(sw_addr(s_x, wt * 32 + n2 * 16 + bRow, kk + bK), d);
                B[n2 * 2][0] = d[0]; B[n2 * 2][1] = d[1];
                B[n2 * 2 + 1][0] = d[2]; B[n2 * 2 + 1][1] = d[3];
            }
#pragma unroll
            for (int ot = 0; ot < 4; ot++)
#pragma unroll
                for (int nt = 0; nt < 4; nt++) mma_bf16(acc[ot][nt], A[ot], B[nt]);
            if (!IS_PROJ) {
                uint32_t Bl[4][2];
#pragma unroll
                for (int n2 = 0; n2 < 2; n2++) {
                    uint32_t d[4];
                    ldsm4(sw_addr(st + 24576, wt * 32 + n2 * 16 + bRow, kk + bK), d);
                    Bl[n2 * 2][0] = d[0]; Bl[n2 * 2][1] = d[1];
                    Bl[n2 * 2 + 1][0] = d[2]; Bl[n2 * 2 + 1][1] = d[3];
                }
#pragma unroll
                for (int ot = 0; ot < 4; ot++)
#pragma unroll
                    for (int nt = 0; nt < 4; nt++) mma_bf16(acc[ot][nt], A[ot], Bl[nt]);
            }
            // reuse A registers for Wl fragments
#pragma unroll
            for (int ot = 0; ot < 4; ot++)
                ldsm4(sw_addr(st + 8192, oh * 64 + ot * 16 + aRow, kk + aK), A[ot]);
#pragma unroll
            for (int ot = 0; ot < 4; ot++)
#pragma unroll
                for (int nt = 0; nt < 4; nt++) mma_bf16(acc[ot][nt], A[ot], B[nt]);
        }
    }

    // ---- epilogue: acc -> ys[4t][128o][33] (smem), then BN + LIF
    __syncthreads();
    float* ys = (float*)SM;
    {
        const int cg = lane >> 2, ctg = lane & 3;
#pragma unroll
        for (int ot = 0; ot < 4; ot++)
#pragma unroll
            for (int nt = 0; nt < 4; nt++) {
                int row = oh * 64 + ot * 16 + cg, col = nt * 8 + ctg * 2;
                ys[(wt * 128 + row) * 33 + col]         = acc[ot][nt][0];
                ys[(wt * 128 + row) * 33 + col + 1]     = acc[ot][nt][1];
                ys[(wt * 128 + row + 8) * 33 + col]     = acc[ot][nt][2];
                ys[(wt * 128 + row + 8) * 33 + col + 1] = acc[ot][nt][3];
            }
    }
    __syncthreads();

    if (!IS_PROJ) {
        // warp: oq2 = warp&3 -> 32 o lanes; ng = warp>>2 -> 16 n each
        const int oq2 = warp & 3, ng = warp >> 2;
        const int o_loc = oq2 * 32 + lane;
        const int og = o128 + o_loc;
        const int br = og >> 9, o_in = og & 511;
        const float inv = g_inv[br * 512 + o_in], shf = g_shift[br * 512 + o_in];
        const int h = (o_in >> 6) & 7, half = (o_loc >> 5) & 1;
#pragma unroll
        for (int j = 0; j < 16; j++) {
            const int nl = ng * 16 + j, n = n0 + nl;
            float v = 0.f;
            bool bad = false, sp[4];
#pragma unroll
            for (int t = 0; t < 4; t++) {
                float y = fmaf(ys[(t * 128 + o_loc) * 33 + nl], inv, shf);
                v += (y - v) * 0.5f;
                float d = v - 1.0f;
                if (fabsf(d) < MARGIN_) bad = true;
                sp[t] = d >= 0.f;
                if (sp[t]) v = 0.f;
            }
#pragma unroll
            for (int t = 0; t < 4; t++) {
                uint32_t m = __ballot_sync(0xffffffffu, sp[t]);
                if (lane == 0)
                    ((uint32_t*)g_bits)[((((size_t)br * 4 + t) * 64 + b) * 8 + h) * 392
                                        + n * 2 + half] = m;
            }
            if (bad) {
                int s = atomicAdd(&g_cnt[0], 1);
                if (s < CAP0)
                    g_fix0[s] = ((unsigned)br << 23) | ((unsigned)b << 17) |
                                ((unsigned)o_in << 8) | n;
            }
        }
    } else {
        // warp -> 16 o rows, lane -> n (coalesced stores)
        const int n = n0 + lane;
#pragma unroll
        for (int j = 0; j < 16; j++) {
            const int o_in = o128 + warp * 16 + j;
            const float inv = g_inv[1536 + o_in], shf = g_shift[1536 + o_in];
            float v = 0.f;
            bool bad = false;
#pragma unroll
            for (int t = 0; t < 4; t++) {
                float y = fmaf(ys[(t * 128 + warp * 16 + j) * 33 + lane], inv, shf);
                v += (y - v) * 0.5f;
                float d = v - 1.0f;
                if (fabsf(d) < MARGIN_) bad = true;
                bool s = d >= 0.f;
                o_out[((size_t)(t * 64 + b) * 512 + o_in) * 196 + n] = s ? 1.f : 0.f;
                if (s) v = 0.f;
            }
            if (bad) {
                int s = atomicAdd(&g_cnt[1], 1);
                if (s < CAP1)
                    g_fix1[s] = ((unsigned)b << 17) | ((unsigned)o_in << 8) | n;
            }
        }
    }
}

// ---------------------------------------------------------------------------
// Fixup: exact fp32 recompute, STRICT sequential c=0..511 order (reference-
// matching). QKV patches g_bits bitwise; proj patches o_out.
// ---------------------------------------------------------------------------
template<int IS_PROJ>
__global__ void fixup(const float* __restrict__ w, float* __restrict__ o_out) {
    int cnt = g_cnt[IS_PROJ];
    int cap = IS_PROJ ? CAP1 : CAP0;
    if (cnt > cap) cnt = cap;
    for (int e = blockIdx.x * blockDim.x + threadIdx.x; e < cnt;
         e += gridDim.x * blockDim.x) {
        unsigned u = IS_PROJ ? g_fix1[e] : g_fix0[e];
        int n = u & 255, o = (u >> 8) & 511, bb = (u >> 17) & 63;
        int br = IS_PROJ ? 3 : (int)(u >> 23);
        const float* wr = w + ((size_t)br * 512 + o) * 512;
        float inv = g_inv[br * 512 + o], shf = g_shift[br * 512 + o];
        float v = 0.f;
#pragma unroll 1
        for (int t = 0; t < 4; t++) {
            float s = 0.f;
            if (IS_PROJ) {
                const __nv_bfloat16* xr = g_s2h + ((size_t)((t * 64 + bb) * 196 + n)) * 512;
#pragma unroll 4
                for (int c = 0; c < 512; c += 2) {
                    __nv_bfloat162 p = *(const __nv_bfloat162*)(xr + c);
                    s = fmaf(wr[c],     __low2float(p),  s);
                    s = fmaf(wr[c + 1], __high2float(p), s);
                }
            } else {
                const float* xr = g_xT + ((size_t)((t * 64 + bb) * 196 + n)) * 512;
#pragma unroll 4
                for (int c = 0; c < 512; c += 4) {
                    float4 a  = *(const float4*)(wr + c);
                    float4 xv = *(const float4*)(xr + c);
                    s = fmaf(a.x, xv.x, s);
                    s = fmaf(a.y, xv.y, s);
                    s = fmaf(a.z, xv.z, s);
                    s = fmaf(a.w, xv.w, s);
                }
            }
            float y = fmaf(s, inv, shf);
            v += (y - v) * 0.5f;
            bool sp = (v - 1.0f) >= 0.f;
            if (IS_PROJ) {
                o_out[((size_t)(t * 64 + bb) * 512 + o) * 196 + n] = sp ? 1.f : 0.f;
            } else {
                int h = o >> 6, d = o & 63;
                uint32_t* wp = ((uint32_t*)g_bits) +
                    ((((size_t)br * 4 + t) * 64 + bb) * 8 + h) * 392 + n * 2 + (d >> 5);
                uint32_t m = 1u << (d & 31);
                if (sp) atomicOr(wp, m); else atomicAnd(wp, ~m);
            }
            if (sp) v = 0.f;
        }
    }
}

// ---------------------------------------------------------------------------
// Attention per (b,h), all 4 t in-block. Exact integer popcount math.
// ---------------------------------------------------------------------------
__global__ __launch_bounds__(512) void attn_kernel(float* __restrict__ attn_out) {
    const int bh = blockIdx.x;
    const int b = bh >> 3, h = bh & 7;

    __shared__ unsigned long long sq[200], sk[200], sv[200];
    __shared__ unsigned long long kcol[64][4], vcol[64][4];
    __shared__ unsigned short s_cnt[4096];
    __shared__ unsigned char  s_spk[64 * 212];

    const int tid = threadIdx.x;
    const int d = tid & 63, g = tid >> 6;

    float vst[25];
#pragma unroll
    for (int j = 0; j < 25; j++) vst[j] = 0.f;

    for (int t = 0; t < 4; t++) {
        size_t qidx = ((size_t)(t * 64 + b) * 8 + h) * 196;
        for (int i = tid; i < 600; i += 512) {
            if (i < 196)      sq[i]       = g_bits[qidx + i];
            else if (i < 392) sk[i - 196] = g_bits[BR_BITS + qidx + (i - 196)];
            else if (i < 588) sv[i - 392] = g_bits[2 * BR_BITS + qidx + (i - 392)];
            else {
                int j = i - 588;
                if (j < 4)      sq[196 + j] = 0ull;
                else if (j < 8) sk[192 + j] = 0ull;
                else            sv[188 + j] = 0ull;
            }
        }
        __syncthreads();
        {
            int e = tid & 63, wd = (tid >> 6) & 3, sel = tid >> 8;
            const unsigned long long* src = sel ? sv : sk;
            int m0 = wd * 64;
            int m1 = m0 + 64 < 196 ? m0 + 64 : 196;
            unsigned long long a = 0ull;
            for (int m = m0; m < m1; m++)
                a |= ((src[m] >> e) & 1ull) << (m - m0);
            if (sel) vcol[e][wd] = a; else kcol[e][wd] = a;
        }
        __syncthreads();
        size_t abase = ((size_t)(t * 64 + b) * 8 + h) * 38416;
        for (int i = tid; i < 38416; i += 512) {
            int n = i / 196; int m = i - n * 196;
            attn_out[abase + i] = (float)__popcll(sq[n] & sk[m]) * 0.125f;
        }
        for (int i = tid; i < 4096; i += 512) {
            int e = i >> 6, dd = i & 63;
            int s = __popcll(kcol[e][0] & vcol[dd][0]) + __popcll(kcol[e][1] & vcol[dd][1])
                  + __popcll(kcol[e][2] & vcol[dd][2]) + __popcll(kcol[e][3] & vcol[dd][3]);
            s_cnt[i] = (unsigned short)s;
        }
        __syncthreads();
#pragma unroll 1
        for (int j = 0; j < 25; j++) {
            int n = g + 8 * j;
            if (n < 196) {
                unsigned long long q = sq[n];
                int sum = 0;
                while (q) {
                    int e = __ffsll((long long)q) - 1;
                    q &= q - 1;
                    sum += s_cnt[(e << 6) + d];
                }
                float o1 = (float)sum * 0.125f;
                float vv = vst[j];
                vv += (o1 - vv) * 0.5f;
                bool s = (vv >= 0.5f);
                vst[j] = s ? 0.f : vv;
                s_spk[d * 212 + n] = s ? 1 : 0;
            }
        }
        __syncthreads();
        // flush spikes as bf16 (exact), layout [t,b,n,c] for the proj GEMM
        for (int i = tid; i < 196 * 64; i += 512) {
            int n = i >> 6, dd = i & 63;
            g_s2h[((size_t)((t * 64 + b) * 196 + n)) * 512 + h * 64 + dd] =
                __float2bfloat16((float)s_spk[dd * 212 + n]);
        }
        __syncthreads();
    }
}

// ---------------------------------------------------------------------------
extern "C" void kernel_launch(void* const* d_in, const int* in_sizes, int n_in,
                              void* d_out, int out_size) {
    const float* x     = (const float*)d_in[0];
    const float* w     = (const float*)d_in[2];
    const float* gamma = (const float*)d_in[3];
    const float* beta  = (const float*)d_in[4];
    const float* mean  = (const float*)d_in[5];
    const float* var   = (const float*)d_in[6];

    float* o_out    = (float*)d_out;
    float* attn_out = o_out + O_ELEMS;

    cudaFuncSetAttribute(mma_gemm_lif<0>, cudaFuncAttributeMaxDynamicSharedMemorySize, SMEMSZ);
    cudaFuncSetAttribute(mma_gemm_lif<1>, cudaFuncAttributeMaxDynamicSharedMemorySize, SMEMSZ);

    prep_bn<<<8, 256>>>(gamma, beta, mean, var);                // 1 (zeroes g_cnt)
    w_split<<<4096, 256>>>(w);                                  // 2
    x_split<<<dim3(16, 7, 256), dim3(32, 8)>>>(x);              // 3
    mma_gemm_lif<0><<<dim3(7, 12, 64), 256, SMEMSZ>>>(nullptr); // 4 <- ncu captures this
    fixup<0><<<256, 256>>>(w, nullptr);
    attn_kernel<<<512, 512>>>(attn_out);
    mma_gemm_lif<1><<<dim3(7, 4, 64), 256, SMEMSZ>>>(o_out);
    fixup<1><<<64, 256>>>(w, o_out);
}